// round 3
// baseline (speedup 1.0000x reference)
#include <cuda_runtime.h>
#include <math.h>
#include <limits.h>

#define NMESH  256
#define MSTEPS 4096
#define SLEN   (MSTEPS + 1)     // scan steps 0..M (step 0 = pseudo init sweep-up at hc=1.0)
#define SLEN2  4104             // padded stride (multiple of 8)
#define LOGS   13
#define TRI    (NMESH * (NMESH + 1) / 2)
#define SENT   ((short)32767)

// ---------------- device scratch ----------------
__device__ float  g_P[TRI];                   // per-row inclusive prefix of softplus density
__device__ float  g_rowsum[NMESH];
__device__ int    g_il[SLEN];                 // packed per-step: (iu << 16) | (link+1)
__device__ short  g_lastup[SLEN];             // last up-step index <= s
__device__ short  g_STd[LOGS * SLEN2];        // sparse table: range-min over down thresholds
__device__ float  g_A[NMESH + 1];             // prefix of rowsums; g_A[NMESH] = S
__device__ float  g_colpreT[NMESH * NMESH];   // colpreT[k*N+j] = sum_{r=j..k} P_r(j)

__device__ __forceinline__ float softplusf(float x) {
    return fmaxf(x, 0.f) + log1pf(expf(-fabsf(x)));
}

// ---------------- K1: per-row softplus + inclusive prefix scan ----------------
__global__ void k_rowprefix(const float* __restrict__ raw) {
    __shared__ float ws[8];
    int i = blockIdx.x, j = threadIdx.x;
    int off = i * (i + 1) / 2;
    float v = 0.f;
    if (j <= i) v = softplusf(raw[off + j]);
    int lane = j & 31, w = j >> 5;
#pragma unroll
    for (int o = 1; o < 32; o <<= 1) { float u = __shfl_up_sync(0xffffffffu, v, o); if (lane >= o) v += u; }
    if (lane == 31) ws[w] = v;
    __syncthreads();
    if (w == 0) {
        float x = (lane < 8) ? ws[lane] : 0.f;
#pragma unroll
        for (int o = 1; o < 8; o <<= 1) { float u = __shfl_up_sync(0xffffffffu, x, o); if (lane >= o) x += u; }
        if (lane < 8) ws[lane] = x;
    }
    __syncthreads();
    if (w > 0) v += ws[w - 1];
    if (j <= i) {
        g_P[off + j] = v;
        if (j == i) g_rowsum[i] = v;
    }
}

// ---------------- K2: single-block metadata kernel (all smem work) ----------------
// dyn smem layout: fsc[32] f32 | sc[1024] int | lin[256] f32 |
//                  st_u[LOGS*SLEN2] s16 | s_iu | s_d | bufA | bufB (each SLEN2 s16)
#define SMEM_META (32*4 + 1024*4 + 256*4 + 2 * (LOGS * SLEN2 + 4 * SLEN2))

__global__ void k_meta(const float* __restrict__ h,
                       const float* __restrict__ m2,
                       const float* __restrict__ m3) {
    extern __shared__ char sraw[];
    float*  fsc = (float*)sraw;
    int*    sc  = (int*)(fsc + 32);
    float*  lin = (float*)(sc + 1024);
    short*  st_u = (short*)(lin + 256);
    short*  s_iu = st_u + LOGS * SLEN2;
    short*  s_d  = s_iu + SLEN2;
    short*  bufA = s_d + SLEN2;
    short*  bufB = bufA + SLEN2;
    int tid = threadIdx.x;

    // ---- phase 0: transposed column-prefix table (coalesced ld+st, fp32) ----
    {
        float a = 0.f;
#pragma unroll 4
        for (int k = 0; k < NMESH; k++) {
            if (tid <= k) {
                a += g_P[k * (k + 1) / 2 + tid];
                g_colpreT[k * NMESH + tid] = a;
            }
        }
    }

    // lin = linspace(-1,1,N) -> pick the mesh whose row 0 varies (xx)
    if (tid < NMESH) {
        const float* xx = (m2[1] != m2[0]) ? m2 : m3;
        lin[tid] = xx[tid];
    }
    __syncthreads();

    // ---- per-step classification: exact float compares against real mesh ----
    for (int s = tid; s < SLEN; s += 1024) {
        float hc, hp;
        if (s == 0) { hc = 1.0f; hp = h[MSTEPS - 1]; }
        else { hc = h[s - 1]; hp = (s == 1) ? 1.0f : h[s - 2]; }
        short iu = 0, dd = SENT;
        if (hc > hp) {             // sweep up: rows with alpha < hc reset full
            int lo = 0, hi = NMESH;
            while (lo < hi) { int m = (lo + hi) >> 1; if (lin[m] < hc) lo = m + 1; else hi = m; }
            iu = (short)lo;
        } else if (hc < hp) {      // sweep down: clamp c to max j with beta_j <= hc
            int lo = 0, hi = NMESH;
            while (lo < hi) { int m = (lo + hi) >> 1; if (lin[m] <= hc) lo = m + 1; else hi = m; }
            dd = (short)(lo - 1);
        }
        s_iu[s] = iu; s_d[s] = dd;
    }
    __syncthreads();

    // ---- lastup: inclusive max-scan of (up ? s : -1) ----
    {
        int base = tid * 4;
        int w0 = (s_iu[base]     > 0) ? base     : -1;
        int w1 = (s_iu[base + 1] > 0) ? base + 1 : -1;
        int w2 = (s_iu[base + 2] > 0) ? base + 2 : -1;
        int w3 = (s_iu[base + 3] > 0) ? base + 3 : -1;
        int l0 = w0, l1 = max(l0, w1), l2 = max(l1, w2), l3 = max(l2, w3);
        sc[tid] = l3;
        __syncthreads();
        for (int o = 1; o < 1024; o <<= 1) {
            int v = sc[tid];
            if (tid >= o) v = max(v, sc[tid - o]);
            __syncthreads();
            sc[tid] = v;
            __syncthreads();
        }
        int pre = (tid > 0) ? sc[tid - 1] : -1;
        g_lastup[base]     = (short)max(pre, l0);
        g_lastup[base + 1] = (short)max(pre, l1);
        g_lastup[base + 2] = (short)max(pre, l2);
        g_lastup[base + 3] = (short)max(pre, l3);
        if (tid == 1023) {
            int w4 = (s_iu[4096] > 0) ? 4096 : -1;
            g_lastup[4096] = (short)max(sc[1023], w4);
        }
    }
    __syncthreads();

    // ---- sparse table over d (min): ping-pong in smem, stream levels to global ----
    {
        short *cur = s_d, *nxt = bufA;
        for (int i = tid; i < SLEN; i += 1024) g_STd[i] = cur[i];
        __syncthreads();
        for (int k = 1; k < LOGS; k++) {
            int half = 1 << (k - 1);
            for (int i = tid; i < SLEN; i += 1024) {
                short a = cur[i];
                short b = (i + half < SLEN) ? cur[i + half] : SENT;
                short m = a < b ? a : b;
                nxt[i] = m;
                g_STd[k * SLEN2 + i] = m;
            }
            __syncthreads();
            short* t = cur; cur = nxt; nxt = (nxt == bufA) ? bufB : bufA;
            (void)t;
        }
    }
    __syncthreads();

    // ---- sparse table over iu (max), resident in smem only ----
    {
        for (int i = tid; i < SLEN; i += 1024) st_u[i] = s_iu[i];
        __syncthreads();
        for (int k = 1; k < LOGS; k++) {
            int half = 1 << (k - 1);
            const short* prv = st_u + (k - 1) * SLEN2;
            short* nxt = st_u + k * SLEN2;
            for (int i = tid; i < SLEN; i += 1024) {
                short a = prv[i];
                short b = (i + half < SLEN) ? prv[i + half] : (short)-1;
                nxt[i] = a > b ? a : b;
            }
            __syncthreads();
        }
    }

    // ---- PGE links + packed il word: rightmost s' < s with iu[s'] > iu[s] ----
    for (int s = tid; s < SLEN; s += 1024) {
        int iu = s_iu[s];
        int lnk = -1;
        if (iu > 0 && iu < NMESH - 1) {
            int L = 0, R = s - 1;
            while (L < R) {
                int mid = (L + R + 1) >> 1;
                int len = R - mid + 1;
                int k = 31 - __clz(len);
                int mx = max((int)st_u[k * SLEN2 + mid], (int)st_u[k * SLEN2 + R - (1 << k) + 1]);
                if (mx > iu) L = mid; else R = mid - 1;
            }
            lnk = L;
        }
        g_il[s] = (iu << 16) | ((lnk + 1) & 0xffff);
    }

    // ---- A prefix of rowsums (fp32) ----
    {
        float v = (tid < NMESH) ? g_rowsum[tid] : 0.f;
        int lane = tid & 31, w = tid >> 5;
#pragma unroll
        for (int o = 1; o < 32; o <<= 1) { float u = __shfl_up_sync(0xffffffffu, v, o); if (lane >= o) v += u; }
        if (lane == 31 && w < 8) fsc[w] = v;
        __syncthreads();
        if (w == 0) {
            float x = (lane < 8) ? fsc[lane] : 0.f;
#pragma unroll
            for (int o = 1; o < 8; o <<= 1) { float u = __shfl_up_sync(0xffffffffu, x, o); if (lane >= o) x += u; }
            if (lane < 8) fsc[lane] = x;
        }
        __syncthreads();
        if (w > 0 && w < 8) v += fsc[w - 1];
        if (tid < NMESH) g_A[tid + 1] = v;
        if (tid == 0) g_A[0] = 0.f;
    }
}

// ---------------- K3: chain walk; only the dependence chain lives in smem ----------------
__global__ void k_main(float* __restrict__ out) {
    __shared__ int   s_il[SLEN];          // 16388 B
    __shared__ float s_A[NMESH + 1];
    for (int i = threadIdx.x; i < SLEN; i += blockDim.x) s_il[i] = g_il[i];
    for (int i = threadIdx.x; i <= NMESH; i += blockDim.x) s_A[i] = g_A[i];
    __syncthreads();

    int t = blockIdx.x * blockDim.x + threadIdx.x;
    if (t >= MSTEPS) return;
    int T = t + 1;
    int s = g_lastup[T];
    int Vmin = INT_MAX;
    int lo = 0, right = T;
    float acc = 0.f;
    while (true) {
        if (s < right) {           // min d over (s, right]  (off the control chain)
            int l = s + 1, r = right;
            int k = 31 - __clz(r - l + 1);
            int m1 = g_STd[k * SLEN2 + l];
            int m2 = g_STd[k * SLEN2 + r - (1 << k) + 1];
            Vmin = min(Vmin, min(m1, m2));
        }
        int il = s_il[s];          // single LDS on the chain
        int hi = il >> 16;         // group rows [lo, hi) share clamp Vmin; c_i = min(i, Vmin)
        if (Vmin >= hi - 1) {
            acc += s_A[hi] - s_A[lo];
        } else if (Vmin >= 0) {
            int m = max(lo, Vmin + 1);
            acc += s_A[m] - s_A[lo];
            acc += g_colpreT[(hi - 1) * NMESH + Vmin] - g_colpreT[(m - 1) * NMESH + Vmin];
        }
        if (hi >= NMESH - 1) break;   // row 255 is always all -1
        lo = hi;
        right = s;
        s = (il & 0xffff) - 1;
    }
    float S = s_A[NMESH];
    out[t] = (2.f * acc - S) / S;
}

// ---------------- launch ----------------
extern "C" void kernel_launch(void* const* d_in, const int* in_sizes, int n_in,
                              void* d_out, int out_size) {
    const float* h   = nullptr;
    const float* raw = nullptr;
    const float* m2  = nullptr;
    const float* m3  = nullptr;
    for (int i = 0; i < n_in; i++) {
        if (in_sizes[i] == MSTEPS && !h)            h   = (const float*)d_in[i];
        else if (in_sizes[i] == TRI && !raw)        raw = (const float*)d_in[i];
        else if (in_sizes[i] == NMESH * NMESH) {
            if (!m2) m2 = (const float*)d_in[i];
            else     m3 = (const float*)d_in[i];
        }
    }
    if (!m3) m3 = m2;

    static bool attr_done = false;
    if (!attr_done) {
        cudaFuncSetAttribute(k_meta, cudaFuncAttributeMaxDynamicSharedMemorySize, SMEM_META);
        attr_done = true;
    }

    k_rowprefix<<<NMESH, NMESH>>>(raw);
    k_meta<<<1, 1024, SMEM_META>>>(h, m2, m3);
    k_main<<<32, 128>>>((float*)d_out);
}

// round 4
// speedup vs baseline: 2.1926x; 2.1926x over previous
#include <cuda_runtime.h>
#include <math.h>
#include <limits.h>

#define NMESH  256
#define MSTEPS 4096
#define SLEN   (MSTEPS + 1)     // scan steps 0..M (step 0 = pseudo init sweep-up at hc=1.0)
#define SLEN2  4104             // padded stride (multiple of 8)
#define LOGS   13
#define TRI    (NMESH * (NMESH + 1) / 2)
#define SENT   ((short)32767)

// ---------------- device scratch ----------------
__device__ float  g_P[TRI];                   // per-row inclusive prefix of softplus density
__device__ float  g_rowsum[NMESH];
__device__ int    g_il[SLEN];                 // packed per-step: (iu << 16) | (link+1)
__device__ short  g_lastup[SLEN];             // last up-step index <= s
__device__ short  g_STd[LOGS * SLEN2];        // sparse table: range-min over down thresholds
__device__ float  g_A[NMESH + 1];             // prefix of rowsums; g_A[NMESH] = S
__device__ float  g_colpreT[NMESH * NMESH];   // colpreT[k*N+j] = sum_{r=j..k} P_r(j)

__device__ __forceinline__ float softplusf(float x) {
    return fmaxf(x, 0.f) + log1pf(expf(-fabsf(x)));
}

// ---------------- K1: per-row softplus + inclusive prefix scan ----------------
__global__ void k_rowprefix(const float* __restrict__ raw) {
    __shared__ float ws[8];
    int i = blockIdx.x, j = threadIdx.x;
    int off = i * (i + 1) / 2;
    float v = 0.f;
    if (j <= i) v = softplusf(raw[off + j]);
    int lane = j & 31, w = j >> 5;
#pragma unroll
    for (int o = 1; o < 32; o <<= 1) { float u = __shfl_up_sync(0xffffffffu, v, o); if (lane >= o) v += u; }
    if (lane == 31) ws[w] = v;
    __syncthreads();
    if (w == 0) {
        float x = (lane < 8) ? ws[lane] : 0.f;
#pragma unroll
        for (int o = 1; o < 8; o <<= 1) { float u = __shfl_up_sync(0xffffffffu, x, o); if (lane >= o) x += u; }
        if (lane < 8) ws[lane] = x;
    }
    __syncthreads();
    if (w > 0) v += ws[w - 1];
    if (j <= i) {
        g_P[off + j] = v;
        if (j == i) g_rowsum[i] = v;
    }
}

// ---------------- K2: column prefix table (parallel, fp32, transposed store) ----------------
__global__ void k_colpre() {
    __shared__ float ws[8];
    int jc = blockIdx.x, k = threadIdx.x;
    float v = (k >= jc) ? g_P[k * (k + 1) / 2 + jc] : 0.f;
    int lane = k & 31, w = k >> 5;
#pragma unroll
    for (int o = 1; o < 32; o <<= 1) { float u = __shfl_up_sync(0xffffffffu, v, o); if (lane >= o) v += u; }
    if (lane == 31) ws[w] = v;
    __syncthreads();
    if (w == 0) {
        float x = (lane < 8) ? ws[lane] : 0.f;
#pragma unroll
        for (int o = 1; o < 8; o <<= 1) { float u = __shfl_up_sync(0xffffffffu, x, o); if (lane >= o) x += u; }
        if (lane < 8) ws[lane] = x;
    }
    __syncthreads();
    if (w > 0) v += ws[w - 1];
    g_colpreT[k * NMESH + jc] = v;   // valid where k >= jc; others never read
}

// ---------------- K3: single-block metadata kernel (all smem work) ----------------
// dyn smem layout: fsc[32] f32 | sc[32] int | lin[256] f32 |
//                  st_u[LOGS*SLEN2] s16 | s_iu | s_d | bufA | bufB (each SLEN2 s16)
#define SMEM_META (32*4 + 32*4 + 256*4 + 2 * (LOGS * SLEN2 + 4 * SLEN2))

__global__ void k_meta(const float* __restrict__ h,
                       const float* __restrict__ m2,
                       const float* __restrict__ m3) {
    extern __shared__ char sraw[];
    float*  fsc = (float*)sraw;
    int*    sc  = (int*)(fsc + 32);
    float*  lin = (float*)(sc + 32);
    short*  st_u = (short*)(lin + 256);
    short*  s_iu = st_u + LOGS * SLEN2;
    short*  s_d  = s_iu + SLEN2;
    short*  bufA = s_d + SLEN2;
    short*  bufB = bufA + SLEN2;
    int tid = threadIdx.x;
    int lane = tid & 31, w = tid >> 5;

    // lin = linspace(-1,1,N) -> pick the mesh whose row 0 varies (xx)
    if (tid < NMESH) {
        const float* xx = (m2[1] != m2[0]) ? m2 : m3;
        lin[tid] = xx[tid];
    }
    __syncthreads();

    // ---- per-step classification: exact float compares against real mesh ----
    for (int s = tid; s < SLEN; s += 1024) {
        float hc, hp;
        if (s == 0) { hc = 1.0f; hp = h[MSTEPS - 1]; }
        else { hc = h[s - 1]; hp = (s == 1) ? 1.0f : h[s - 2]; }
        short iu = 0, dd = SENT;
        if (hc > hp) {             // sweep up: rows with alpha < hc reset full
            int lo = 0, hi = NMESH;
            while (lo < hi) { int m = (lo + hi) >> 1; if (lin[m] < hc) lo = m + 1; else hi = m; }
            iu = (short)lo;
        } else if (hc < hp) {      // sweep down: clamp c to max j with beta_j <= hc
            int lo = 0, hi = NMESH;
            while (lo < hi) { int m = (lo + hi) >> 1; if (lin[m] <= hc) lo = m + 1; else hi = m; }
            dd = (short)(lo - 1);
        }
        s_iu[s] = iu; s_d[s] = dd;
    }
    __syncthreads();

    // ---- lastup: inclusive max-scan of (up ? s : -1), shfl-based (2 barriers) ----
    {
        int base = tid * 4;
        int w0 = (s_iu[base]     > 0) ? base     : -1;
        int w1 = (s_iu[base + 1] > 0) ? base + 1 : -1;
        int w2 = (s_iu[base + 2] > 0) ? base + 2 : -1;
        int w3 = (s_iu[base + 3] > 0) ? base + 3 : -1;
        int l0 = w0, l1 = max(l0, w1), l2 = max(l1, w2), l3 = max(l2, w3);
        int v = l3;
#pragma unroll
        for (int o = 1; o < 32; o <<= 1) { int u = __shfl_up_sync(0xffffffffu, v, o); if (lane >= o) v = max(v, u); }
        if (lane == 31) sc[w] = v;
        __syncthreads();
        if (w == 0) {
            int x = sc[lane];
#pragma unroll
            for (int o = 1; o < 32; o <<= 1) { int u = __shfl_up_sync(0xffffffffu, x, o); if (lane >= o) x = max(x, u); }
            sc[lane] = x;
        }
        __syncthreads();
        int warppre = (w > 0) ? sc[w - 1] : INT_MIN;
        int lanepre = __shfl_up_sync(0xffffffffu, v, 1);   // inclusive of lane-1
        int pre = (lane == 0) ? warppre : max(warppre, lanepre);
        g_lastup[base]     = (short)max(pre, l0);
        g_lastup[base + 1] = (short)max(pre, l1);
        g_lastup[base + 2] = (short)max(pre, l2);
        g_lastup[base + 3] = (short)max(pre, l3);
        if (tid == 1023) {
            int w4 = (s_iu[4096] > 0) ? 4096 : -1;
            g_lastup[4096] = (short)max(max(pre, l3), w4);
        }
    }
    __syncthreads();

    // ---- sparse table over d (min): ping-pong in smem, stream levels to global ----
    {
        short *cur = s_d, *nxt = bufA;
        for (int i = tid; i < SLEN; i += 1024) g_STd[i] = cur[i];
        __syncthreads();
        for (int k = 1; k < LOGS; k++) {
            int half = 1 << (k - 1);
            for (int i = tid; i < SLEN; i += 1024) {
                short a = cur[i];
                short b = (i + half < SLEN) ? cur[i + half] : SENT;
                short m = a < b ? a : b;
                nxt[i] = m;
                g_STd[k * SLEN2 + i] = m;
            }
            __syncthreads();
            short* t = cur; cur = nxt; nxt = (nxt == bufA) ? bufB : bufA;
            (void)t;
        }
    }
    __syncthreads();

    // ---- sparse table over iu (max), resident in smem only ----
    {
        for (int i = tid; i < SLEN; i += 1024) st_u[i] = s_iu[i];
        __syncthreads();
        for (int k = 1; k < LOGS; k++) {
            int half = 1 << (k - 1);
            const short* prv = st_u + (k - 1) * SLEN2;
            short* nxt = st_u + k * SLEN2;
            for (int i = tid; i < SLEN; i += 1024) {
                short a = prv[i];
                short b = (i + half < SLEN) ? prv[i + half] : (short)-1;
                nxt[i] = a > b ? a : b;
            }
            __syncthreads();
        }
    }

    // ---- PGE links + packed il word: rightmost s' < s with iu[s'] > iu[s] ----
    for (int s = tid; s < SLEN; s += 1024) {
        int iu = s_iu[s];
        int lnk = -1;
        if (iu > 0 && iu < NMESH - 1) {
            int L = 0, R = s - 1;
            while (L < R) {
                int mid = (L + R + 1) >> 1;
                int len = R - mid + 1;
                int k = 31 - __clz(len);
                int mx = max((int)st_u[k * SLEN2 + mid], (int)st_u[k * SLEN2 + R - (1 << k) + 1]);
                if (mx > iu) L = mid; else R = mid - 1;
            }
            lnk = L;
        }
        g_il[s] = (iu << 16) | ((lnk + 1) & 0xffff);
    }

    // ---- A prefix of rowsums (fp32) ----
    {
        float v = (tid < NMESH) ? g_rowsum[tid] : 0.f;
#pragma unroll
        for (int o = 1; o < 32; o <<= 1) { float u = __shfl_up_sync(0xffffffffu, v, o); if (lane >= o) v += u; }
        if (lane == 31 && w < 8) fsc[w] = v;
        __syncthreads();
        if (w == 0) {
            float x = (lane < 8) ? fsc[lane] : 0.f;
#pragma unroll
            for (int o = 1; o < 8; o <<= 1) { float u = __shfl_up_sync(0xffffffffu, x, o); if (lane >= o) x += u; }
            if (lane < 8) fsc[lane] = x;
        }
        __syncthreads();
        if (w > 0 && w < 8) v += fsc[w - 1];
        if (tid < NMESH) g_A[tid + 1] = v;
        if (tid == 0) g_A[0] = 0.f;
    }
}

// ---------------- K4: chain walk; only the dependence chain lives in smem ----------------
__global__ void k_main(float* __restrict__ out) {
    __shared__ int   s_il[SLEN];          // 16388 B
    __shared__ float s_A[NMESH + 1];
    for (int i = threadIdx.x; i < SLEN; i += blockDim.x) s_il[i] = g_il[i];
    for (int i = threadIdx.x; i <= NMESH; i += blockDim.x) s_A[i] = g_A[i];
    __syncthreads();

    int t = blockIdx.x * blockDim.x + threadIdx.x;
    if (t >= MSTEPS) return;
    int T = t + 1;
    int s = g_lastup[T];
    int Vmin = INT_MAX;
    int lo = 0, right = T;
    float acc = 0.f;
    while (true) {
        if (s < right) {           // min d over (s, right]  (off the control chain)
            int l = s + 1, r = right;
            int k = 31 - __clz(r - l + 1);
            int m1 = g_STd[k * SLEN2 + l];
            int m2 = g_STd[k * SLEN2 + r - (1 << k) + 1];
            Vmin = min(Vmin, min(m1, m2));
        }
        int il = s_il[s];          // single LDS on the chain
        int hi = il >> 16;         // group rows [lo, hi) share clamp Vmin; c_i = min(i, Vmin)
        if (Vmin >= hi - 1) {
            acc += s_A[hi] - s_A[lo];
        } else if (Vmin >= 0) {
            int m = max(lo, Vmin + 1);
            acc += s_A[m] - s_A[lo];
            acc += g_colpreT[(hi - 1) * NMESH + Vmin] - g_colpreT[(m - 1) * NMESH + Vmin];
        }
        if (hi >= NMESH - 1) break;   // row 255 is always all -1
        lo = hi;
        right = s;
        s = (il & 0xffff) - 1;
    }
    float S = s_A[NMESH];
    out[t] = (2.f * acc - S) / S;
}

// ---------------- launch ----------------
extern "C" void kernel_launch(void* const* d_in, const int* in_sizes, int n_in,
                              void* d_out, int out_size) {
    const float* h   = nullptr;
    const float* raw = nullptr;
    const float* m2  = nullptr;
    const float* m3  = nullptr;
    for (int i = 0; i < n_in; i++) {
        if (in_sizes[i] == MSTEPS && !h)            h   = (const float*)d_in[i];
        else if (in_sizes[i] == TRI && !raw)        raw = (const float*)d_in[i];
        else if (in_sizes[i] == NMESH * NMESH) {
            if (!m2) m2 = (const float*)d_in[i];
            else     m3 = (const float*)d_in[i];
        }
    }
    if (!m3) m3 = m2;

    cudaFuncSetAttribute(k_meta, cudaFuncAttributeMaxDynamicSharedMemorySize, SMEM_META);

    k_rowprefix<<<NMESH, NMESH>>>(raw);
    k_colpre<<<NMESH, NMESH>>>();
    k_meta<<<1, 1024, SMEM_META>>>(h, m2, m3);
    k_main<<<32, 128>>>((float*)d_out);
}

// round 5
// speedup vs baseline: 2.1945x; 1.0009x over previous
#include <cuda_runtime.h>
#include <math.h>
#include <limits.h>

#define NMESH  256
#define MSTEPS 4096
#define SLEN   (MSTEPS + 1)     // scan steps 0..M (step 0 = pseudo init sweep-up at hc=1.0)
#define SLEN2  4104             // padded stride (multiple of 8)
#define LOGS   13
#define TRI    (NMESH * (NMESH + 1) / 2)
#define SENT   ((short)32767)
#define CHUNK  8

// ---------------- device scratch ----------------
__device__ float  g_P[TRI];                   // per-row inclusive prefix of softplus density
__device__ float  g_rowsum[NMESH];
__device__ int    g_il[SLEN];                 // packed per-step: (iu << 16) | (link+1)
__device__ short  g_lastup[SLEN];             // last up-step index <= s
__device__ short  g_STd[LOGS * SLEN2];        // sparse table: range-min over down thresholds
__device__ float  g_A[NMESH + 1];             // prefix of rowsums; g_A[NMESH] = S
__device__ float  g_colpreT[NMESH * NMESH];   // colpreT[k*N+j] = sum_{r=j..k} P_r(j)

__device__ __forceinline__ float softplusf(float x) {
    return fmaxf(x, 0.f) + log1pf(expf(-fabsf(x)));
}

// ---------------- K1: per-row softplus + inclusive prefix scan ----------------
__global__ void k_rowprefix(const float* __restrict__ raw) {
    __shared__ float ws[8];
    int i = blockIdx.x, j = threadIdx.x;
    int off = i * (i + 1) / 2;
    float v = 0.f;
    if (j <= i) v = softplusf(raw[off + j]);
    int lane = j & 31, w = j >> 5;
#pragma unroll
    for (int o = 1; o < 32; o <<= 1) { float u = __shfl_up_sync(0xffffffffu, v, o); if (lane >= o) v += u; }
    if (lane == 31) ws[w] = v;
    __syncthreads();
    if (w == 0) {
        float x = (lane < 8) ? ws[lane] : 0.f;
#pragma unroll
        for (int o = 1; o < 8; o <<= 1) { float u = __shfl_up_sync(0xffffffffu, x, o); if (lane >= o) x += u; }
        if (lane < 8) ws[lane] = x;
    }
    __syncthreads();
    if (w > 0) v += ws[w - 1];
    if (j <= i) {
        g_P[off + j] = v;
        if (j == i) g_rowsum[i] = v;
    }
}

// ---------------- K2: column prefix table (parallel, fp32, transposed store) ----------------
__global__ void k_colpre() {
    __shared__ float ws[8];
    int jc = blockIdx.x, k = threadIdx.x;
    float v = (k >= jc) ? g_P[k * (k + 1) / 2 + jc] : 0.f;
    int lane = k & 31, w = k >> 5;
#pragma unroll
    for (int o = 1; o < 32; o <<= 1) { float u = __shfl_up_sync(0xffffffffu, v, o); if (lane >= o) v += u; }
    if (lane == 31) ws[w] = v;
    __syncthreads();
    if (w == 0) {
        float x = (lane < 8) ? ws[lane] : 0.f;
#pragma unroll
        for (int o = 1; o < 8; o <<= 1) { float u = __shfl_up_sync(0xffffffffu, x, o); if (lane >= o) x += u; }
        if (lane < 8) ws[lane] = x;
    }
    __syncthreads();
    if (w > 0) v += ws[w - 1];
    g_colpreT[k * NMESH + jc] = v;   // valid where k >= jc; others never read
}

// ---------------- K3: single-block metadata kernel (all smem work) ----------------
#define SMEM_META (32*4 + 32*4 + 256*4 + 2 * (LOGS * SLEN2 + 4 * SLEN2))

__global__ void k_meta(const float* __restrict__ h,
                       const float* __restrict__ m2,
                       const float* __restrict__ m3) {
    extern __shared__ char sraw[];
    float*  fsc = (float*)sraw;
    int*    sc  = (int*)(fsc + 32);
    float*  lin = (float*)(sc + 32);
    short*  st_u = (short*)(lin + 256);
    short*  s_iu = st_u + LOGS * SLEN2;
    short*  s_d  = s_iu + SLEN2;
    short*  bufA = s_d + SLEN2;
    short*  bufB = bufA + SLEN2;
    int tid = threadIdx.x;
    int lane = tid & 31, w = tid >> 5;

    if (tid < NMESH) {
        const float* xx = (m2[1] != m2[0]) ? m2 : m3;
        lin[tid] = xx[tid];
    }
    __syncthreads();

    // ---- per-step classification: exact float compares against real mesh ----
    for (int s = tid; s < SLEN; s += 1024) {
        float hc, hp;
        if (s == 0) { hc = 1.0f; hp = h[MSTEPS - 1]; }
        else { hc = h[s - 1]; hp = (s == 1) ? 1.0f : h[s - 2]; }
        short iu = 0, dd = SENT;
        if (hc > hp) {
            int lo = 0, hi = NMESH;
            while (lo < hi) { int m = (lo + hi) >> 1; if (lin[m] < hc) lo = m + 1; else hi = m; }
            iu = (short)lo;
        } else if (hc < hp) {
            int lo = 0, hi = NMESH;
            while (lo < hi) { int m = (lo + hi) >> 1; if (lin[m] <= hc) lo = m + 1; else hi = m; }
            dd = (short)(lo - 1);
        }
        s_iu[s] = iu; s_d[s] = dd;
    }
    __syncthreads();

    // ---- lastup: inclusive max-scan of (up ? s : -1), shfl-based ----
    {
        int base = tid * 4;
        int w0 = (s_iu[base]     > 0) ? base     : -1;
        int w1 = (s_iu[base + 1] > 0) ? base + 1 : -1;
        int w2 = (s_iu[base + 2] > 0) ? base + 2 : -1;
        int w3 = (s_iu[base + 3] > 0) ? base + 3 : -1;
        int l0 = w0, l1 = max(l0, w1), l2 = max(l1, w2), l3 = max(l2, w3);
        int v = l3;
#pragma unroll
        for (int o = 1; o < 32; o <<= 1) { int u = __shfl_up_sync(0xffffffffu, v, o); if (lane >= o) v = max(v, u); }
        if (lane == 31) sc[w] = v;
        __syncthreads();
        if (w == 0) {
            int x = sc[lane];
#pragma unroll
            for (int o = 1; o < 32; o <<= 1) { int u = __shfl_up_sync(0xffffffffu, x, o); if (lane >= o) x = max(x, u); }
            sc[lane] = x;
        }
        __syncthreads();
        int warppre = (w > 0) ? sc[w - 1] : INT_MIN;
        int lanepre = __shfl_up_sync(0xffffffffu, v, 1);
        int pre = (lane == 0) ? warppre : max(warppre, lanepre);
        g_lastup[base]     = (short)max(pre, l0);
        g_lastup[base + 1] = (short)max(pre, l1);
        g_lastup[base + 2] = (short)max(pre, l2);
        g_lastup[base + 3] = (short)max(pre, l3);
        if (tid == 1023) {
            int w4 = (s_iu[4096] > 0) ? 4096 : -1;
            g_lastup[4096] = (short)max(max(pre, l3), w4);
        }
    }
    __syncthreads();

    // ---- sparse table over d (min): ping-pong in smem, stream levels to global ----
    {
        short *cur = s_d, *nxt = bufA;
        for (int i = tid; i < SLEN; i += 1024) g_STd[i] = cur[i];
        __syncthreads();
        for (int k = 1; k < LOGS; k++) {
            int half = 1 << (k - 1);
            for (int i = tid; i < SLEN; i += 1024) {
                short a = cur[i];
                short b = (i + half < SLEN) ? cur[i + half] : SENT;
                short m = a < b ? a : b;
                nxt[i] = m;
                g_STd[k * SLEN2 + i] = m;
            }
            __syncthreads();
            short* t = cur; cur = nxt; nxt = (nxt == bufA) ? bufB : bufA;
            (void)t;
        }
    }
    __syncthreads();

    // ---- sparse table over iu (max), resident in smem only ----
    {
        for (int i = tid; i < SLEN; i += 1024) st_u[i] = s_iu[i];
        __syncthreads();
        for (int k = 1; k < LOGS; k++) {
            int half = 1 << (k - 1);
            const short* prv = st_u + (k - 1) * SLEN2;
            short* nxt = st_u + k * SLEN2;
            for (int i = tid; i < SLEN; i += 1024) {
                short a = prv[i];
                short b = (i + half < SLEN) ? prv[i + half] : (short)-1;
                nxt[i] = a > b ? a : b;
            }
            __syncthreads();
        }
    }

    // ---- PGE links + packed il word ----
    for (int s = tid; s < SLEN; s += 1024) {
        int iu = s_iu[s];
        int lnk = -1;
        if (iu > 0 && iu < NMESH - 1) {
            int L = 0, R = s - 1;
            while (L < R) {
                int mid = (L + R + 1) >> 1;
                int len = R - mid + 1;
                int k = 31 - __clz(len);
                int mx = max((int)st_u[k * SLEN2 + mid], (int)st_u[k * SLEN2 + R - (1 << k) + 1]);
                if (mx > iu) L = mid; else R = mid - 1;
            }
            lnk = L;
        }
        g_il[s] = (iu << 16) | ((lnk + 1) & 0xffff);
    }

    // ---- A prefix of rowsums (fp32) ----
    {
        float v = (tid < NMESH) ? g_rowsum[tid] : 0.f;
#pragma unroll
        for (int o = 1; o < 32; o <<= 1) { float u = __shfl_up_sync(0xffffffffu, v, o); if (lane >= o) v += u; }
        if (lane == 31 && w < 8) fsc[w] = v;
        __syncthreads();
        if (w == 0) {
            float x = (lane < 8) ? fsc[lane] : 0.f;
#pragma unroll
            for (int o = 1; o < 8; o <<= 1) { float u = __shfl_up_sync(0xffffffffu, x, o); if (lane >= o) x += u; }
            if (lane < 8) fsc[lane] = x;
        }
        __syncthreads();
        if (w > 0 && w < 8) v += fsc[w - 1];
        if (tid < NMESH) g_A[tid + 1] = v;
        if (tid == 0) g_A[0] = 0.f;
    }
}

// ---------------- K4: chunked chain walk with batched independent loads ----------------
__global__ void k_main(float* __restrict__ out) {
    __shared__ int   s_il[SLEN];          // 16388 B
    __shared__ float s_A[NMESH + 1];
    for (int i = threadIdx.x; i < SLEN; i += blockDim.x) s_il[i] = g_il[i];
    for (int i = threadIdx.x; i <= NMESH; i += blockDim.x) s_A[i] = g_A[i];
    __syncthreads();

    int t = blockIdx.x * blockDim.x + threadIdx.x;
    if (t >= MSTEPS) return;
    int T = t + 1;
    int s = g_lastup[T];
    int right = T;
    int lo = 0;
    int Vcarry = INT_MAX;
    float acc = 0.f;
    bool finished = false;

    while (!finished) {
        // ---- Phase A: LDS-only pointer chase, record chunk ----
        int ssk[CHUNK], rrk[CHUNK], hik[CHUNK];
        int cnt = 0;
        bool done = false;
#pragma unroll
        for (int c = 0; c < CHUNK; c++) {
            if (!done) {
                int il = s_il[s];
                int hi = il >> 16;
                ssk[c] = s; rrk[c] = right; hik[c] = hi;
                cnt = c + 1;
                if (hi >= NMESH - 1) { done = true; }
                else { right = s; s = (il & 0xffff) - 1; }
            }
        }

        // ---- Phase B: all STd RMQ loads for the chunk, independent ----
        int D[CHUNK];
#pragma unroll
        for (int c = 0; c < CHUNK; c++) {
            D[c] = INT_MAX;
            if (c < cnt && ssk[c] < rrk[c]) {
                int l = ssk[c] + 1, r = rrk[c];
                int k = 31 - __clz(r - l + 1);
                int m1 = g_STd[k * SLEN2 + l];
                int m2 = g_STd[k * SLEN2 + r - (1 << k) + 1];
                D[c] = min(m1, m2);
            }
        }

        // ---- Phase C: prefix-min -> Vmin per level; batched colpre loads; accumulate ----
        int Vm[CHUNK];
        {
            int v = Vcarry;
#pragma unroll
            for (int c = 0; c < CHUNK; c++) { v = min(v, D[c]); Vm[c] = v; }
            Vcarry = v;
        }
#pragma unroll
        for (int c = 0; c < CHUNK; c++) {
            if (c < cnt) {
                int hi = hik[c];
                int V = Vm[c];
                int lolocal = (c == 0) ? lo : hik[c - 1];
                if (V >= hi - 1) {
                    acc += s_A[hi] - s_A[lolocal];
                } else if (V >= 0) {
                    int m = max(lolocal, V + 1);
                    acc += s_A[m] - s_A[lolocal];
                    acc += g_colpreT[(hi - 1) * NMESH + V] - g_colpreT[(m - 1) * NMESH + V];
                }
            }
        }
        lo = hik[cnt - 1];
        finished = done;
    }

    float S = s_A[NMESH];
    out[t] = (2.f * acc - S) / S;
}

// ---------------- launch ----------------
extern "C" void kernel_launch(void* const* d_in, const int* in_sizes, int n_in,
                              void* d_out, int out_size) {
    const float* h   = nullptr;
    const float* raw = nullptr;
    const float* m2  = nullptr;
    const float* m3  = nullptr;
    for (int i = 0; i < n_in; i++) {
        if (in_sizes[i] == MSTEPS && !h)            h   = (const float*)d_in[i];
        else if (in_sizes[i] == TRI && !raw)        raw = (const float*)d_in[i];
        else if (in_sizes[i] == NMESH * NMESH) {
            if (!m2) m2 = (const float*)d_in[i];
            else     m3 = (const float*)d_in[i];
        }
    }
    if (!m3) m3 = m2;

    cudaFuncSetAttribute(k_meta, cudaFuncAttributeMaxDynamicSharedMemorySize, SMEM_META);

    k_rowprefix<<<NMESH, NMESH>>>(raw);
    k_colpre<<<NMESH, NMESH>>>();
    k_meta<<<1, 1024, SMEM_META>>>(h, m2, m3);
    k_main<<<32, 128>>>((float*)d_out);
}

// round 6
// speedup vs baseline: 2.3713x; 1.0806x over previous
#include <cuda_runtime.h>
#include <math.h>
#include <limits.h>

#define NMESH  256
#define MSTEPS 4096
#define SLEN   (MSTEPS + 1)     // scan steps 0..M (step 0 = pseudo init sweep-up at hc=1.0)
#define SLEN2  4104             // padded stride (multiple of 8)
#define LOGS   13
#define TRI    (NMESH * (NMESH + 1) / 2)
#define SENT   ((short)32767)
#define CHUNK  8
#define ILPAD  4112             // SLEN padded to multiple of 4 for uint4 copy

// ---------------- device scratch ----------------
__device__ float  g_P[TRI];                   // per-row inclusive prefix of softplus density
__device__ float  g_rowsum[NMESH];
__device__ int    g_il[ILPAD];                // packed per-step: (iu << 16) | (link+1)
__device__ short  g_lastup[SLEN];             // last up-step index <= s
__device__ short  g_STd[LOGS * SLEN2];        // sparse table: range-min over down thresholds
__device__ float  g_A[NMESH + 1];             // prefix of rowsums; g_A[NMESH] = S
__device__ float  g_colpreT[NMESH * NMESH];   // colpreT[k*N+j] = sum_{r=j..k} P_r(j)

__device__ __forceinline__ float softplusf(float x) {
    return fmaxf(x, 0.f) + log1pf(expf(-fabsf(x)));
}

// ---------------- K1: per-row softplus + inclusive prefix scan ----------------
__global__ void k_rowprefix(const float* __restrict__ raw) {
    __shared__ float ws[8];
    int i = blockIdx.x, j = threadIdx.x;
    int off = i * (i + 1) / 2;
    float v = 0.f;
    if (j <= i) v = softplusf(raw[off + j]);
    int lane = j & 31, w = j >> 5;
#pragma unroll
    for (int o = 1; o < 32; o <<= 1) { float u = __shfl_up_sync(0xffffffffu, v, o); if (lane >= o) v += u; }
    if (lane == 31) ws[w] = v;
    __syncthreads();
    if (w == 0) {
        float x = (lane < 8) ? ws[lane] : 0.f;
#pragma unroll
        for (int o = 1; o < 8; o <<= 1) { float u = __shfl_up_sync(0xffffffffu, x, o); if (lane >= o) x += u; }
        if (lane < 8) ws[lane] = x;
    }
    __syncthreads();
    if (w > 0) v += ws[w - 1];
    if (j <= i) {
        g_P[off + j] = v;
        if (j == i) g_rowsum[i] = v;
    }
}

// ---------------- K2: column prefix table + (block 256) A prefix ----------------
__global__ void k_colpre() {
    __shared__ float ws[8];
    int k = threadIdx.x;
    int lane = k & 31, w = k >> 5;

    if (blockIdx.x == NMESH) {
        // A prefix of rowsums
        float v = g_rowsum[k];
#pragma unroll
        for (int o = 1; o < 32; o <<= 1) { float u = __shfl_up_sync(0xffffffffu, v, o); if (lane >= o) v += u; }
        if (lane == 31) ws[w] = v;
        __syncthreads();
        if (w == 0) {
            float x = (lane < 8) ? ws[lane] : 0.f;
#pragma unroll
            for (int o = 1; o < 8; o <<= 1) { float u = __shfl_up_sync(0xffffffffu, x, o); if (lane >= o) x += u; }
            if (lane < 8) ws[lane] = x;
        }
        __syncthreads();
        if (w > 0) v += ws[w - 1];
        g_A[k + 1] = v;
        if (k == 0) g_A[0] = 0.f;
        return;
    }

    int jc = blockIdx.x;
    float v = (k >= jc) ? g_P[k * (k + 1) / 2 + jc] : 0.f;
#pragma unroll
    for (int o = 1; o < 32; o <<= 1) { float u = __shfl_up_sync(0xffffffffu, v, o); if (lane >= o) v += u; }
    if (lane == 31) ws[w] = v;
    __syncthreads();
    if (w == 0) {
        float x = (lane < 8) ? ws[lane] : 0.f;
#pragma unroll
        for (int o = 1; o < 8; o <<= 1) { float u = __shfl_up_sync(0xffffffffu, x, o); if (lane >= o) x += u; }
        if (lane < 8) ws[lane] = x;
    }
    __syncthreads();
    if (w > 0) v += ws[w - 1];
    g_colpreT[k * NMESH + jc] = v;   // valid where k >= jc; others never read
}

// ---------------- K3: single-block metadata kernel (no g_P/g_rowsum deps) ----------------
#define SMEM_META (32*4 + 256*4 + 2 * (LOGS * SLEN2 + 4 * SLEN2))

__global__ void k_meta(const float* __restrict__ h,
                       const float* __restrict__ m2,
                       const float* __restrict__ m3) {
    extern __shared__ char sraw[];
    int*    sc  = (int*)sraw;
    float*  lin = (float*)(sc + 32);
    short*  st_u = (short*)(lin + 256);
    short*  s_iu = st_u + LOGS * SLEN2;
    short*  s_d  = s_iu + SLEN2;
    short*  bufA = s_d + SLEN2;
    short*  bufB = bufA + SLEN2;
    int tid = threadIdx.x;
    int lane = tid & 31, w = tid >> 5;

    if (tid < NMESH) {
        const float* xx = (m2[1] != m2[0]) ? m2 : m3;
        lin[tid] = xx[tid];
    }
    __syncthreads();

    // ---- per-step classification: exact float compares against real mesh ----
    for (int s = tid; s < SLEN; s += 1024) {
        float hc, hp;
        if (s == 0) { hc = 1.0f; hp = h[MSTEPS - 1]; }
        else { hc = h[s - 1]; hp = (s == 1) ? 1.0f : h[s - 2]; }
        short iu = 0, dd = SENT;
        if (hc > hp) {
            int lo = 0, hi = NMESH;
            while (lo < hi) { int m = (lo + hi) >> 1; if (lin[m] < hc) lo = m + 1; else hi = m; }
            iu = (short)lo;
        } else if (hc < hp) {
            int lo = 0, hi = NMESH;
            while (lo < hi) { int m = (lo + hi) >> 1; if (lin[m] <= hc) lo = m + 1; else hi = m; }
            dd = (short)(lo - 1);
        }
        s_iu[s] = iu; s_d[s] = dd;
    }
    __syncthreads();

    // ---- lastup: inclusive max-scan of (up ? s : -1), shfl-based ----
    {
        int base = tid * 4;
        int w0 = (s_iu[base]     > 0) ? base     : -1;
        int w1 = (s_iu[base + 1] > 0) ? base + 1 : -1;
        int w2 = (s_iu[base + 2] > 0) ? base + 2 : -1;
        int w3 = (s_iu[base + 3] > 0) ? base + 3 : -1;
        int l0 = w0, l1 = max(l0, w1), l2 = max(l1, w2), l3 = max(l2, w3);
        int v = l3;
#pragma unroll
        for (int o = 1; o < 32; o <<= 1) { int u = __shfl_up_sync(0xffffffffu, v, o); if (lane >= o) v = max(v, u); }
        if (lane == 31) sc[w] = v;
        __syncthreads();
        if (w == 0) {
            int x = sc[lane];
#pragma unroll
            for (int o = 1; o < 32; o <<= 1) { int u = __shfl_up_sync(0xffffffffu, x, o); if (lane >= o) x = max(x, u); }
            sc[lane] = x;
        }
        __syncthreads();
        int warppre = (w > 0) ? sc[w - 1] : INT_MIN;
        int lanepre = __shfl_up_sync(0xffffffffu, v, 1);
        int pre = (lane == 0) ? warppre : max(warppre, lanepre);
        g_lastup[base]     = (short)max(pre, l0);
        g_lastup[base + 1] = (short)max(pre, l1);
        g_lastup[base + 2] = (short)max(pre, l2);
        g_lastup[base + 3] = (short)max(pre, l3);
        if (tid == 1023) {
            int w4 = (s_iu[4096] > 0) ? 4096 : -1;
            g_lastup[4096] = (short)max(max(pre, l3), w4);
        }
    }
    __syncthreads();

    // ---- fused sparse tables: STd (min, ping-pong + stream to global), STu (max, resident) ----
    {
        for (int i = tid; i < SLEN; i += 1024) { g_STd[i] = s_d[i]; st_u[i] = s_iu[i]; }
        __syncthreads();
        short *cur = s_d, *nxt = bufA;
        for (int k = 1; k < LOGS; k++) {
            int half = 1 << (k - 1);
            const short* prvU = st_u + (k - 1) * SLEN2;
            short* nxtU = st_u + k * SLEN2;
            for (int i = tid; i < SLEN; i += 1024) {
                short a = cur[i];
                short b = (i + half < SLEN) ? cur[i + half] : SENT;
                short m = a < b ? a : b;
                nxt[i] = m;
                g_STd[k * SLEN2 + i] = m;
                short ua = prvU[i];
                short ub = (i + half < SLEN) ? prvU[i + half] : (short)-1;
                nxtU[i] = ua > ub ? ua : ub;
            }
            __syncthreads();
            short* t = cur; cur = nxt; nxt = (nxt == bufA) ? bufB : bufA;
            (void)t;
        }
    }

    // ---- PGE links + packed il word ----
    for (int s = tid; s < SLEN; s += 1024) {
        int iu = s_iu[s];
        int lnk = -1;
        if (iu > 0 && iu < NMESH - 1) {
            int L = 0, R = s - 1;
            while (L < R) {
                int mid = (L + R + 1) >> 1;
                int len = R - mid + 1;
                int k = 31 - __clz(len);
                int mx = max((int)st_u[k * SLEN2 + mid], (int)st_u[k * SLEN2 + R - (1 << k) + 1]);
                if (mx > iu) L = mid; else R = mid - 1;
            }
            lnk = L;
        }
        g_il[s] = (iu << 16) | ((lnk + 1) & 0xffff);
    }
    // zero the uint4 padding tail
    if (tid < ILPAD - SLEN) g_il[SLEN + tid] = 0;
}

// ---------------- K4: chunked chain walk, register-resident, batched loads ----------------
__global__ void __launch_bounds__(128) k_main(float* __restrict__ out) {
    __shared__ int   s_il[ILPAD];
    __shared__ float s_A[NMESH + 1];

    int t = blockIdx.x * blockDim.x + threadIdx.x;
    int T = t + 1;
    int s0 = (t < MSTEPS) ? (int)g_lastup[T] : 0;   // issue early

    {
        const uint4* src = (const uint4*)g_il;
        uint4* dst = (uint4*)s_il;
#pragma unroll
        for (int i = threadIdx.x; i < ILPAD / 4; i += 128) dst[i] = src[i];
        for (int i = threadIdx.x; i <= NMESH; i += 128) s_A[i] = g_A[i];
    }
    __syncthreads();
    if (t >= MSTEPS) return;

    int s = s0, right = T, lo = 0, Vcarry = INT_MAX;
    float acc = 0.f;
    bool finished = false;

    while (!finished) {
        // ---- Phase A: LDS-only pointer chase (static indexing everywhere) ----
        int ssk[CHUNK], rrk[CHUNK], hik[CHUNK];
        bool act[CHUNK];
        bool done = false;
        int lastHi = lo;
#pragma unroll
        for (int c = 0; c < CHUNK; c++) {
            act[c] = !done;
            if (!done) {
                int il = s_il[s];
                int hi = il >> 16;
                ssk[c] = s; rrk[c] = right; hik[c] = hi;
                lastHi = hi;
                if (hi >= NMESH - 1) done = true;
                else { right = s; s = (il & 0xffff) - 1; }
            } else {
                ssk[c] = 0; rrk[c] = 0; hik[c] = 0;
            }
        }

        // ---- Phase B: all STd RMQ loads, independent (one L2 round trip) ----
        int D[CHUNK];
#pragma unroll
        for (int c = 0; c < CHUNK; c++) {
            D[c] = INT_MAX;
            if (ssk[c] < rrk[c]) {
                int l = ssk[c] + 1, r = rrk[c];
                int k = 31 - __clz(r - l + 1);
                int m1 = g_STd[k * SLEN2 + l];
                int m2 = g_STd[k * SLEN2 + r - (1 << k) + 1];
                D[c] = min(m1, m2);
            }
        }

        // ---- Phase C: prefix-min -> Vmin; batched colpre loads; accumulate ----
        int Vm[CHUNK];
        {
            int v = Vcarry;
#pragma unroll
            for (int c = 0; c < CHUNK; c++) { v = min(v, D[c]); Vm[c] = v; }
            Vcarry = v;
        }
#pragma unroll
        for (int c = 0; c < CHUNK; c++) {
            if (act[c]) {
                int hi = hik[c];
                int V = Vm[c];
                int lol = (c == 0) ? lo : hik[c - 1];
                if (V >= hi - 1) {
                    acc += s_A[hi] - s_A[lol];
                } else if (V >= 0) {
                    int m = max(lol, V + 1);
                    acc += s_A[m] - s_A[lol];
                    acc += g_colpreT[(hi - 1) * NMESH + V] - g_colpreT[(m - 1) * NMESH + V];
                }
            }
        }
        lo = lastHi;
        finished = done;
    }

    float S = s_A[NMESH];
    out[t] = (2.f * acc - S) / S;
}

// ---------------- launch: fork k_meta onto a side stream ----------------
extern "C" void kernel_launch(void* const* d_in, const int* in_sizes, int n_in,
                              void* d_out, int out_size) {
    const float* h   = nullptr;
    const float* raw = nullptr;
    const float* m2  = nullptr;
    const float* m3  = nullptr;
    for (int i = 0; i < n_in; i++) {
        if (in_sizes[i] == MSTEPS && !h)            h   = (const float*)d_in[i];
        else if (in_sizes[i] == TRI && !raw)        raw = (const float*)d_in[i];
        else if (in_sizes[i] == NMESH * NMESH) {
            if (!m2) m2 = (const float*)d_in[i];
            else     m3 = (const float*)d_in[i];
        }
    }
    if (!m3) m3 = m2;

    static cudaStream_t s1 = nullptr;
    static cudaEvent_t evF = nullptr, evM = nullptr;
    if (!s1) {
        cudaStreamCreateWithFlags(&s1, cudaStreamNonBlocking);
        cudaEventCreateWithFlags(&evF, cudaEventDisableTiming);
        cudaEventCreateWithFlags(&evM, cudaEventDisableTiming);
        cudaFuncSetAttribute(k_meta, cudaFuncAttributeMaxDynamicSharedMemorySize, SMEM_META);
    }

    // fork: k_meta depends only on h/mesh -> run concurrently with k1->k2
    cudaEventRecord(evF, 0);
    cudaStreamWaitEvent(s1, evF, 0);
    k_meta<<<1, 1024, SMEM_META, s1>>>(h, m2, m3);
    cudaEventRecord(evM, s1);

    k_rowprefix<<<NMESH, NMESH>>>(raw);
    k_colpre<<<NMESH + 1, NMESH>>>();

    // join, then main
    cudaStreamWaitEvent(0, evM, 0);
    k_main<<<MSTEPS / 128, 128>>>((float*)d_out);
}

// round 7
// speedup vs baseline: 2.3801x; 1.0037x over previous
#include <cuda_runtime.h>
#include <math.h>
#include <limits.h>

#define NMESH  256
#define MSTEPS 4096
#define SLEN   (MSTEPS + 1)     // scan steps 0..M (step 0 = pseudo init sweep-up at hc=1.0)
#define SLEN2  4104             // padded stride (multiple of 8)
#define LOGS   13
#define TRI    (NMESH * (NMESH + 1) / 2)
#define SENT   ((short)32767)
#define CHUNK  8
#define ILPAD  4112             // SLEN padded to multiple of 4 for uint4 copy

// ---------------- device scratch ----------------
__device__ float  g_P[TRI];                   // per-row inclusive prefix of softplus density
__device__ float  g_rowsum[NMESH];
__device__ int    g_il[ILPAD];                // packed: (iu:9)<<22 | (link+1:13)<<9 | (segMin+1:9)
__device__ int    g_start[SLEN];              // packed: lastup<<9 | (dminLast+1)
__device__ short  g_STd[LOGS * SLEN2];        // sparse table: range-min over down thresholds
__device__ float  g_A[NMESH + 1];             // prefix of rowsums; g_A[NMESH] = S
__device__ float  g_colpreT[NMESH * NMESH];   // colpreT[k*N+j] = sum_{r=j..k} P_r(j)

__device__ __forceinline__ float softplusf(float x) {
    return fmaxf(x, 0.f) + log1pf(expf(-fabsf(x)));
}

// ---------------- K1: per-row softplus + inclusive prefix scan ----------------
__global__ void k_rowprefix(const float* __restrict__ raw) {
    __shared__ float ws[8];
    int i = blockIdx.x, j = threadIdx.x;
    int off = i * (i + 1) / 2;
    float v = 0.f;
    if (j <= i) v = softplusf(raw[off + j]);
    int lane = j & 31, w = j >> 5;
#pragma unroll
    for (int o = 1; o < 32; o <<= 1) { float u = __shfl_up_sync(0xffffffffu, v, o); if (lane >= o) v += u; }
    if (lane == 31) ws[w] = v;
    __syncthreads();
    if (w == 0) {
        float x = (lane < 8) ? ws[lane] : 0.f;
#pragma unroll
        for (int o = 1; o < 8; o <<= 1) { float u = __shfl_up_sync(0xffffffffu, x, o); if (lane >= o) x += u; }
        if (lane < 8) ws[lane] = x;
    }
    __syncthreads();
    if (w > 0) v += ws[w - 1];
    if (j <= i) {
        g_P[off + j] = v;
        if (j == i) g_rowsum[i] = v;
    }
}

// ---------------- K2: column prefix table + (block 256) A prefix ----------------
__global__ void k_colpre() {
    __shared__ float ws[8];
    int k = threadIdx.x;
    int lane = k & 31, w = k >> 5;

    if (blockIdx.x == NMESH) {
        float v = g_rowsum[k];
#pragma unroll
        for (int o = 1; o < 32; o <<= 1) { float u = __shfl_up_sync(0xffffffffu, v, o); if (lane >= o) v += u; }
        if (lane == 31) ws[w] = v;
        __syncthreads();
        if (w == 0) {
            float x = (lane < 8) ? ws[lane] : 0.f;
#pragma unroll
            for (int o = 1; o < 8; o <<= 1) { float u = __shfl_up_sync(0xffffffffu, x, o); if (lane >= o) x += u; }
            if (lane < 8) ws[lane] = x;
        }
        __syncthreads();
        if (w > 0) v += ws[w - 1];
        g_A[k + 1] = v;
        if (k == 0) g_A[0] = 0.f;
        return;
    }

    int jc = blockIdx.x;
    float v = (k >= jc) ? g_P[k * (k + 1) / 2 + jc] : 0.f;
#pragma unroll
    for (int o = 1; o < 32; o <<= 1) { float u = __shfl_up_sync(0xffffffffu, v, o); if (lane >= o) v += u; }
    if (lane == 31) ws[w] = v;
    __syncthreads();
    if (w == 0) {
        float x = (lane < 8) ? ws[lane] : 0.f;
#pragma unroll
        for (int o = 1; o < 8; o <<= 1) { float u = __shfl_up_sync(0xffffffffu, x, o); if (lane >= o) x += u; }
        if (lane < 8) ws[lane] = x;
    }
    __syncthreads();
    if (w > 0) v += ws[w - 1];
    g_colpreT[k * NMESH + jc] = v;   // valid where k >= jc; others never read
}

// ---------------- K3: single-block metadata kernel ----------------
// smem: sc[32] int | lin[256] f32 | st_u[LOGS*SLEN2] | s_iu | s_d | bufA | bufB | s_lu (s16)
#define SMEM_META (32*4 + 256*4 + 2 * (LOGS * SLEN2 + 5 * SLEN2))

__global__ void k_meta(const float* __restrict__ h,
                       const float* __restrict__ m2,
                       const float* __restrict__ m3) {
    extern __shared__ char sraw[];
    int*    sc  = (int*)sraw;
    float*  lin = (float*)(sc + 32);
    short*  st_u = (short*)(lin + 256);
    short*  s_iu = st_u + LOGS * SLEN2;
    short*  s_d  = s_iu + SLEN2;
    short*  bufA = s_d + SLEN2;
    short*  bufB = bufA + SLEN2;
    short*  s_lu = bufB + SLEN2;
    int tid = threadIdx.x;
    int lane = tid & 31, w = tid >> 5;

    if (tid < NMESH) {
        const float* xx = (m2[1] != m2[0]) ? m2 : m3;
        lin[tid] = xx[tid];
    }
    __syncthreads();

    // ---- per-step classification: exact float compares against real mesh ----
    for (int s = tid; s < SLEN; s += 1024) {
        float hc, hp;
        if (s == 0) { hc = 1.0f; hp = h[MSTEPS - 1]; }
        else { hc = h[s - 1]; hp = (s == 1) ? 1.0f : h[s - 2]; }
        short iu = 0, dd = SENT;
        if (hc > hp) {
            int lo = 0, hi = NMESH;
            while (lo < hi) { int m = (lo + hi) >> 1; if (lin[m] < hc) lo = m + 1; else hi = m; }
            iu = (short)lo;
        } else if (hc < hp) {
            int lo = 0, hi = NMESH;
            while (lo < hi) { int m = (lo + hi) >> 1; if (lin[m] <= hc) lo = m + 1; else hi = m; }
            dd = (short)(lo - 1);
        }
        s_iu[s] = iu; s_d[s] = dd;
    }
    __syncthreads();

    // ---- lastup: inclusive max-scan of (up ? s : -1), shfl-based, into smem ----
    {
        int base = tid * 4;
        int w0 = (s_iu[base]     > 0) ? base     : -1;
        int w1 = (s_iu[base + 1] > 0) ? base + 1 : -1;
        int w2 = (s_iu[base + 2] > 0) ? base + 2 : -1;
        int w3 = (s_iu[base + 3] > 0) ? base + 3 : -1;
        int l0 = w0, l1 = max(l0, w1), l2 = max(l1, w2), l3 = max(l2, w3);
        int v = l3;
#pragma unroll
        for (int o = 1; o < 32; o <<= 1) { int u = __shfl_up_sync(0xffffffffu, v, o); if (lane >= o) v = max(v, u); }
        if (lane == 31) sc[w] = v;
        __syncthreads();
        if (w == 0) {
            int x = sc[lane];
#pragma unroll
            for (int o = 1; o < 32; o <<= 1) { int u = __shfl_up_sync(0xffffffffu, x, o); if (lane >= o) x = max(x, u); }
            sc[lane] = x;
        }
        __syncthreads();
        int warppre = (w > 0) ? sc[w - 1] : INT_MIN;
        int lanepre = __shfl_up_sync(0xffffffffu, v, 1);
        int pre = (lane == 0) ? warppre : max(warppre, lanepre);
        s_lu[base]     = (short)max(pre, l0);
        s_lu[base + 1] = (short)max(pre, l1);
        s_lu[base + 2] = (short)max(pre, l2);
        s_lu[base + 3] = (short)max(pre, l3);
        if (tid == 1023) {
            int w4 = (s_iu[4096] > 0) ? 4096 : -1;
            s_lu[4096] = (short)max(max(pre, l3), w4);
        }
    }
    __syncthreads();

    // ---- fused sparse tables: STd (min, ping-pong + stream to global), STu (max, resident) ----
    {
        for (int i = tid; i < SLEN; i += 1024) { g_STd[i] = s_d[i]; st_u[i] = s_iu[i]; }
        __syncthreads();
        short *cur = s_d, *nxt = bufA;
        for (int k = 1; k < LOGS; k++) {
            int half = 1 << (k - 1);
            const short* prvU = st_u + (k - 1) * SLEN2;
            short* nxtU = st_u + k * SLEN2;
            for (int i = tid; i < SLEN; i += 1024) {
                short a = cur[i];
                short b = (i + half < SLEN) ? cur[i + half] : SENT;
                short m = a < b ? a : b;
                nxt[i] = m;
                g_STd[k * SLEN2 + i] = m;
                short ua = prvU[i];
                short ub = (i + half < SLEN) ? prvU[i + half] : (short)-1;
                nxtU[i] = ua > ub ? ua : ub;
            }
            __syncthreads();
            short* t = cur; cur = nxt; nxt = (nxt == bufA) ? bufB : bufA;
            (void)t;
        }
    }

    // ---- PGE links + segMin RMQ -> packed il word; g_start per T ----
    for (int s = tid; s < SLEN; s += 1024) {
        int iu = s_iu[s];
        int lnk = -1;
        int e = 257;                              // segMin+1 encoding; 257 = +inf
        if (iu > 0 && iu < NMESH - 1) {
            int L = 0, R = s - 1;
            while (L < R) {
                int mid = (L + R + 1) >> 1;
                int len = R - mid + 1;
                int k = 31 - __clz(len);
                int mx = max((int)st_u[k * SLEN2 + mid], (int)st_u[k * SLEN2 + R - (1 << k) + 1]);
                if (mx > iu) L = mid; else R = mid - 1;
            }
            lnk = L;
            // segMin over (lnk, s]
            int l = lnk + 1, r = s;
            int k = 31 - __clz(r - l + 1);
            int m1 = g_STd[k * SLEN2 + l];
            int m2 = g_STd[k * SLEN2 + r - (1 << k) + 1];
            e = min(min(m1, m2) + 1, 257);
        }
        g_il[s] = (iu << 22) | ((lnk + 1) << 9) | e;

        // g_start: lastup + min d over (lastup, s]
        int lu = s_lu[s];
        int enc = 257;
        if (lu < s) {
            int l = lu + 1, r = s;
            int k = 31 - __clz(r - l + 1);
            int m1 = g_STd[k * SLEN2 + l];
            int m2 = g_STd[k * SLEN2 + r - (1 << k) + 1];
            enc = min(min(m1, m2) + 1, 257);
        }
        g_start[s] = (lu << 9) | enc;
    }
    // zero the uint4 padding tail of g_il
    if (tid < ILPAD - SLEN) g_il[SLEN + tid] = 0;
}

// ---------------- K4: pure-smem chain walk + batched colpre loads ----------------
__global__ void __launch_bounds__(128) k_main(float* __restrict__ out) {
    __shared__ int   s_il[ILPAD];
    __shared__ float s_A[NMESH + 1];

    int t = blockIdx.x * blockDim.x + threadIdx.x;
    int T = t + 1;
    int st = (t < MSTEPS) ? g_start[T] : 0;   // issue early

    {
        const uint4* src = (const uint4*)g_il;
        uint4* dst = (uint4*)s_il;
#pragma unroll
        for (int i = threadIdx.x; i < ILPAD / 4; i += 128) dst[i] = src[i];
        for (int i = threadIdx.x; i <= NMESH; i += 128) s_A[i] = g_A[i];
    }
    __syncthreads();
    if (t >= MSTEPS) return;

    int s = st >> 9;
    int Vmin = (st & 0x1FF) - 1;    // 256 acts as +inf
    int lo = 0;
    float acc = 0.f;
    bool finished = false;

    while (!finished) {
        // ---- Phase A: LDS-only chase; record (lo, hi, V) per level ----
        int hiA[CHUNK], VA[CHUNK], loA[CHUNK];
        bool act[CHUNK];
        bool done = false;
#pragma unroll
        for (int c = 0; c < CHUNK; c++) {
            act[c] = !done;
            if (!done) {
                int il = s_il[s];
                int hi = (unsigned)il >> 22;
                hiA[c] = hi; VA[c] = Vmin; loA[c] = lo;
                if (hi >= NMESH - 1) done = true;
                else {
                    Vmin = min(Vmin, (il & 0x1FF) - 1);
                    s = ((il >> 9) & 0x1FFF) - 1;
                    lo = hi;
                }
            } else { hiA[c] = 0; VA[c] = -1; loA[c] = 0; }
        }

        // ---- Phase B: batched independent colpre/A accumulation ----
        float a0 = 0.f, a1 = 0.f, a2 = 0.f, a3 = 0.f;
#pragma unroll
        for (int c = 0; c < CHUNK; c++) {
            float contrib = 0.f;
            if (act[c]) {
                int hi = hiA[c], V = VA[c], lol = loA[c];
                if (V >= hi - 1) {
                    contrib = s_A[hi] - s_A[lol];
                } else if (V >= 0) {
                    int m = max(lol, V + 1);
                    contrib = s_A[m] - s_A[lol]
                            + g_colpreT[(hi - 1) * NMESH + V]
                            - g_colpreT[(m - 1) * NMESH + V];
                }
            }
            if ((c & 3) == 0) a0 += contrib;
            else if ((c & 3) == 1) a1 += contrib;
            else if ((c & 3) == 2) a2 += contrib;
            else a3 += contrib;
        }
        acc += (a0 + a1) + (a2 + a3);
        finished = done;
    }

    float S = s_A[NMESH];
    out[t] = (2.f * acc - S) / S;
}

// ---------------- launch: fork k_meta onto a side stream ----------------
extern "C" void kernel_launch(void* const* d_in, const int* in_sizes, int n_in,
                              void* d_out, int out_size) {
    const float* h   = nullptr;
    const float* raw = nullptr;
    const float* m2  = nullptr;
    const float* m3  = nullptr;
    for (int i = 0; i < n_in; i++) {
        if (in_sizes[i] == MSTEPS && !h)            h   = (const float*)d_in[i];
        else if (in_sizes[i] == TRI && !raw)        raw = (const float*)d_in[i];
        else if (in_sizes[i] == NMESH * NMESH) {
            if (!m2) m2 = (const float*)d_in[i];
            else     m3 = (const float*)d_in[i];
        }
    }
    if (!m3) m3 = m2;

    static cudaStream_t s1 = nullptr;
    static cudaEvent_t evF = nullptr, evM = nullptr;
    if (!s1) {
        cudaStreamCreateWithFlags(&s1, cudaStreamNonBlocking);
        cudaEventCreateWithFlags(&evF, cudaEventDisableTiming);
        cudaEventCreateWithFlags(&evM, cudaEventDisableTiming);
        cudaFuncSetAttribute(k_meta, cudaFuncAttributeMaxDynamicSharedMemorySize, SMEM_META);
    }

    // fork: k_meta depends only on h/mesh -> run concurrently with k1->k2
    cudaEventRecord(evF, 0);
    cudaStreamWaitEvent(s1, evF, 0);
    k_meta<<<1, 1024, SMEM_META, s1>>>(h, m2, m3);
    cudaEventRecord(evM, s1);

    k_rowprefix<<<NMESH, NMESH>>>(raw);
    k_colpre<<<NMESH + 1, NMESH>>>();

    // join, then main
    cudaStreamWaitEvent(0, evM, 0);
    k_main<<<MSTEPS / 128, 128>>>((float*)d_out);
}

// round 8
// speedup vs baseline: 2.4367x; 1.0238x over previous
#include <cuda_runtime.h>
#include <math.h>
#include <limits.h>

#define NMESH  256
#define MSTEPS 4096
#define SLEN   (MSTEPS + 1)     // scan steps 0..M (step 0 = pseudo init sweep-up at hc=1.0)
#define SLENP  4128             // padded to multiple of 32 (129 chunks)
#define NCH    (SLENP / 32)     // 129
#define TRI    (NMESH * (NMESH + 1) / 2)
#define SENTD  32767
#define CHUNK  8
#define ILPAD  4112             // SLEN padded to multiple of 4 for uint4 copy

// ---------------- device scratch ----------------
__device__ float  g_P[TRI];                   // per-row inclusive prefix of softplus density
__device__ float  g_rowsum[NMESH];
__device__ int    g_il[ILPAD];                // packed: (iu:9)<<22 | (link+1:13)<<9 | (segMin+1:9)
__device__ int    g_start[SLEN];              // packed: lastup<<9 | (dminLast+1)
__device__ float  g_A[NMESH + 1];             // prefix of rowsums; g_A[NMESH] = S
__device__ float  g_colpreT[NMESH * NMESH];   // colpreT[k*N+j] = sum_{r=j..k} P_r(j)

__device__ __forceinline__ float softplusf(float x) {
    return fmaxf(x, 0.f) + log1pf(expf(-fabsf(x)));
}

// ---------------- K1: per-row softplus + inclusive prefix scan ----------------
__global__ void k_rowprefix(const float* __restrict__ raw) {
    __shared__ float ws[8];
    int i = blockIdx.x, j = threadIdx.x;
    int off = i * (i + 1) / 2;
    float v = 0.f;
    if (j <= i) v = softplusf(raw[off + j]);
    int lane = j & 31, w = j >> 5;
#pragma unroll
    for (int o = 1; o < 32; o <<= 1) { float u = __shfl_up_sync(0xffffffffu, v, o); if (lane >= o) v += u; }
    if (lane == 31) ws[w] = v;
    __syncthreads();
    if (w == 0) {
        float x = (lane < 8) ? ws[lane] : 0.f;
#pragma unroll
        for (int o = 1; o < 8; o <<= 1) { float u = __shfl_up_sync(0xffffffffu, x, o); if (lane >= o) x += u; }
        if (lane < 8) ws[lane] = x;
    }
    __syncthreads();
    if (w > 0) v += ws[w - 1];
    if (j <= i) {
        g_P[off + j] = v;
        if (j == i) g_rowsum[i] = v;
    }
}

// ---------------- K2: column prefix table + (block 256) A prefix ----------------
__global__ void k_colpre() {
    __shared__ float ws[8];
    int k = threadIdx.x;
    int lane = k & 31, w = k >> 5;

    if (blockIdx.x == NMESH) {
        float v = g_rowsum[k];
#pragma unroll
        for (int o = 1; o < 32; o <<= 1) { float u = __shfl_up_sync(0xffffffffu, v, o); if (lane >= o) v += u; }
        if (lane == 31) ws[w] = v;
        __syncthreads();
        if (w == 0) {
            float x = (lane < 8) ? ws[lane] : 0.f;
#pragma unroll
            for (int o = 1; o < 8; o <<= 1) { float u = __shfl_up_sync(0xffffffffu, x, o); if (lane >= o) x += u; }
            if (lane < 8) ws[lane] = x;
        }
        __syncthreads();
        if (w > 0) v += ws[w - 1];
        g_A[k + 1] = v;
        if (k == 0) g_A[0] = 0.f;
        return;
    }

    int jc = blockIdx.x;
    float v = (k >= jc) ? g_P[k * (k + 1) / 2 + jc] : 0.f;
#pragma unroll
    for (int o = 1; o < 32; o <<= 1) { float u = __shfl_up_sync(0xffffffffu, v, o); if (lane >= o) v += u; }
    if (lane == 31) ws[w] = v;
    __syncthreads();
    if (w == 0) {
        float x = (lane < 8) ? ws[lane] : 0.f;
#pragma unroll
        for (int o = 1; o < 8; o <<= 1) { float u = __shfl_up_sync(0xffffffffu, x, o); if (lane >= o) x += u; }
        if (lane < 8) ws[lane] = x;
    }
    __syncthreads();
    if (w > 0) v += ws[w - 1];
    g_colpreT[k * NMESH + jc] = v;   // valid where k >= jc; others never read
}

// ---------------- K3: single-block metadata kernel (chunked RMQ, static smem) ----------------
__global__ void __launch_bounds__(1024) k_meta(const float* __restrict__ h,
                                               const float* __restrict__ m2,
                                               const float* __restrict__ m3) {
    __shared__ float lin[NMESH];
    __shared__ short s_iu[SLENP];
    __shared__ short s_d[SLENP];
    __shared__ short s_lu[SLENP];
    __shared__ short pmind[SLENP];   // prefix-min of d within each 32-chunk
    __shared__ short smind[SLENP];   // suffix-min of d within each 32-chunk
    __shared__ short cmind[NCH];     // chunk min of d
    __shared__ short cmaxu[NCH];     // chunk max of iu
    __shared__ int   sc[32];

    int tid = threadIdx.x;
    int lane = tid & 31, w = tid >> 5;

    if (tid < NMESH) {
        const float* xx = (m2[1] != m2[0]) ? m2 : m3;
        lin[tid] = xx[tid];
    }
    __syncthreads();

    // ---- per-step classification (+ padding) ----
    for (int s = tid; s < SLENP; s += 1024) {
        short iu = 0, dd = (short)SENTD;
        if (s < SLEN) {
            float hc, hp;
            if (s == 0) { hc = 1.0f; hp = h[MSTEPS - 1]; }
            else { hc = h[s - 1]; hp = (s == 1) ? 1.0f : h[s - 2]; }
            if (hc > hp) {
                int lo = 0, hi = NMESH;
                while (lo < hi) { int m = (lo + hi) >> 1; if (lin[m] < hc) lo = m + 1; else hi = m; }
                iu = (short)lo;
            } else if (hc < hp) {
                int lo = 0, hi = NMESH;
                while (lo < hi) { int m = (lo + hi) >> 1; if (lin[m] <= hc) lo = m + 1; else hi = m; }
                dd = (short)(lo - 1);
            }
        }
        s_iu[s] = iu; s_d[s] = dd;
    }
    __syncthreads();

    // ---- lastup: inclusive max-scan of (up ? s : -1), shfl-based ----
    {
        int base = tid * 4;
        int w0 = (s_iu[base]     > 0) ? base     : -1;
        int w1 = (s_iu[base + 1] > 0) ? base + 1 : -1;
        int w2 = (s_iu[base + 2] > 0) ? base + 2 : -1;
        int w3 = (s_iu[base + 3] > 0) ? base + 3 : -1;
        int l0 = w0, l1 = max(l0, w1), l2 = max(l1, w2), l3 = max(l2, w3);
        int v = l3;
#pragma unroll
        for (int o = 1; o < 32; o <<= 1) { int u = __shfl_up_sync(0xffffffffu, v, o); if (lane >= o) v = max(v, u); }
        if (lane == 31) sc[w] = v;
        __syncthreads();
        if (w == 0) {
            int x = sc[lane];
#pragma unroll
            for (int o = 1; o < 32; o <<= 1) { int u = __shfl_up_sync(0xffffffffu, x, o); if (lane >= o) x = max(x, u); }
            sc[lane] = x;
        }
        __syncthreads();
        int warppre = (w > 0) ? sc[w - 1] : INT_MIN;
        int lanepre = __shfl_up_sync(0xffffffffu, v, 1);
        int pre = (lane == 0) ? warppre : max(warppre, lanepre);
        s_lu[base]     = (short)max(pre, l0);
        s_lu[base + 1] = (short)max(pre, l1);
        s_lu[base + 2] = (short)max(pre, l2);
        s_lu[base + 3] = (short)max(pre, l3);
        if (tid == 1023) {
            int w4 = (s_iu[4096] > 0) ? 4096 : -1;
            s_lu[4096] = (short)max(max(pre, l3), w4);
        }
    }

    // ---- per-chunk prefix/suffix min of d, chunk min d, chunk max iu ----
    for (int c = w; c < NCH; c += 32) {
        int e = c * 32 + lane;
        int dv = s_d[e];
        int uv = s_iu[e];
        int p = dv;
#pragma unroll
        for (int o = 1; o < 32; o <<= 1) { int u = __shfl_up_sync(0xffffffffu, p, o); if (lane >= o) p = min(p, u); }
        pmind[e] = (short)p;
        int q = dv;
#pragma unroll
        for (int o = 1; o < 32; o <<= 1) { int u = __shfl_down_sync(0xffffffffu, q, o); if (lane + o < 32) q = min(q, u); }
        smind[e] = (short)q;
        if (lane == 31) cmind[c] = (short)p;
        int m = uv;
#pragma unroll
        for (int o = 16; o >= 1; o >>= 1) m = max(m, __shfl_xor_sync(0xffffffffu, m, o));
        if (lane == 0) cmaxu[c] = (short)m;
    }
    __syncthreads();

    // ---- per-step: PGE link + segMin RMQ -> g_il; lastup RMQ -> g_start ----
    for (int s = tid; s < SLEN; s += 1024) {
        int iu = s_iu[s];
        int lnk = -1;
        int e = 257;                              // segMin+1 encoding; 257 = +inf
        if (iu > 0 && iu < NMESH - 1) {
            // PGE: rightmost s' < s with iu[s'] > iu (step 0 has iu=255, terminates)
            int i = s - 1;
            int c = i >> 5;
            int found = -1;
            for (; i >= (c << 5); i--) if ((int)s_iu[i] > iu) { found = i; break; }
            if (found < 0) {
                for (c = c - 1; (int)cmaxu[c] <= iu; c--) {}
                for (i = (c << 5) + 31; ; i--) if ((int)s_iu[i] > iu) { found = i; break; }
            }
            lnk = found;
            // segMin d over [lnk+1, s]
            int l = lnk + 1, r = s;
            int cl = l >> 5, cr = r >> 5;
            int v;
            if (cl == cr) {
                v = SENTD;
                for (int ii = l; ii <= r; ii++) v = min(v, (int)s_d[ii]);
            } else {
                v = min((int)smind[l], (int)pmind[r]);
                for (int cc = cl + 1; cc < cr; cc++) v = min(v, (int)cmind[cc]);
            }
            e = min(v + 1, 257);
        }
        g_il[s] = (iu << 22) | ((lnk + 1) << 9) | e;

        // g_start: lastup + min d over (lastup, s]
        int lu = s_lu[s];
        int enc = 257;
        if (lu < s) {
            int l = lu + 1, r = s;
            int cl = l >> 5, cr = r >> 5;
            int v;
            if (cl == cr) {
                v = SENTD;
                for (int ii = l; ii <= r; ii++) v = min(v, (int)s_d[ii]);
            } else {
                v = min((int)smind[l], (int)pmind[r]);
                for (int cc = cl + 1; cc < cr; cc++) v = min(v, (int)cmind[cc]);
            }
            enc = min(v + 1, 257);
        }
        g_start[s] = (lu << 9) | enc;
    }
    // zero the uint4 padding tail of g_il
    if (tid < ILPAD - SLEN) g_il[SLEN + tid] = 0;
}

// ---------------- K4: pure-smem chain walk + batched colpre loads ----------------
__global__ void __launch_bounds__(256) k_main(float* __restrict__ out) {
    __shared__ int   s_il[ILPAD];
    __shared__ float s_A[NMESH + 1];

    int t = blockIdx.x * blockDim.x + threadIdx.x;
    int T = t + 1;
    int st = (t < MSTEPS) ? g_start[T] : 0;   // issue early

    {
        const uint4* src = (const uint4*)g_il;
        uint4* dst = (uint4*)s_il;
#pragma unroll
        for (int i = threadIdx.x; i < ILPAD / 4; i += 256) dst[i] = src[i];
        for (int i = threadIdx.x; i <= NMESH; i += 256) s_A[i] = g_A[i];
    }
    __syncthreads();
    if (t >= MSTEPS) return;

    int s = st >> 9;
    int Vmin = (st & 0x1FF) - 1;    // 256 acts as +inf
    int lo = 0;
    float acc = 0.f;
    bool finished = false;

    while (!finished) {
        // ---- Phase A: LDS-only chase; record (lo, hi, V) per level ----
        int hiA[CHUNK], VA[CHUNK], loA[CHUNK];
        bool act[CHUNK];
        bool done = false;
#pragma unroll
        for (int c = 0; c < CHUNK; c++) {
            act[c] = !done;
            if (!done) {
                int il = s_il[s];
                int hi = (unsigned)il >> 22;
                hiA[c] = hi; VA[c] = Vmin; loA[c] = lo;
                if (hi >= NMESH - 1) done = true;
                else {
                    Vmin = min(Vmin, (il & 0x1FF) - 1);
                    s = ((il >> 9) & 0x1FFF) - 1;
                    lo = hi;
                }
            } else { hiA[c] = 0; VA[c] = -1; loA[c] = 0; }
        }

        // ---- Phase B: batched independent colpre/A accumulation ----
        float a0 = 0.f, a1 = 0.f, a2 = 0.f, a3 = 0.f;
#pragma unroll
        for (int c = 0; c < CHUNK; c++) {
            float contrib = 0.f;
            if (act[c]) {
                int hi = hiA[c], V = VA[c], lol = loA[c];
                if (V >= hi - 1) {
                    contrib = s_A[hi] - s_A[lol];
                } else if (V >= 0) {
                    int m = max(lol, V + 1);
                    contrib = s_A[m] - s_A[lol]
                            + g_colpreT[(hi - 1) * NMESH + V]
                            - g_colpreT[(m - 1) * NMESH + V];
                }
            }
            if ((c & 3) == 0) a0 += contrib;
            else if ((c & 3) == 1) a1 += contrib;
            else if ((c & 3) == 2) a2 += contrib;
            else a3 += contrib;
        }
        acc += (a0 + a1) + (a2 + a3);
        finished = done;
    }

    float S = s_A[NMESH];
    out[t] = (2.f * acc - S) / S;
}

// ---------------- launch: fork k_meta onto a side stream ----------------
extern "C" void kernel_launch(void* const* d_in, const int* in_sizes, int n_in,
                              void* d_out, int out_size) {
    const float* h   = nullptr;
    const float* raw = nullptr;
    const float* m2  = nullptr;
    const float* m3  = nullptr;
    for (int i = 0; i < n_in; i++) {
        if (in_sizes[i] == MSTEPS && !h)            h   = (const float*)d_in[i];
        else if (in_sizes[i] == TRI && !raw)        raw = (const float*)d_in[i];
        else if (in_sizes[i] == NMESH * NMESH) {
            if (!m2) m2 = (const float*)d_in[i];
            else     m3 = (const float*)d_in[i];
        }
    }
    if (!m3) m3 = m2;

    static cudaStream_t s1 = nullptr;
    static cudaEvent_t evF = nullptr, evM = nullptr;
    if (!s1) {
        cudaStreamCreateWithFlags(&s1, cudaStreamNonBlocking);
        cudaEventCreateWithFlags(&evF, cudaEventDisableTiming);
        cudaEventCreateWithFlags(&evM, cudaEventDisableTiming);
    }

    // fork: k_meta depends only on h/mesh -> run concurrently with k1->k2
    cudaEventRecord(evF, 0);
    cudaStreamWaitEvent(s1, evF, 0);
    k_meta<<<1, 1024, 0, s1>>>(h, m2, m3);
    cudaEventRecord(evM, s1);

    k_rowprefix<<<NMESH, NMESH>>>(raw);
    k_colpre<<<NMESH + 1, NMESH>>>();

    // join, then main
    cudaStreamWaitEvent(0, evM, 0);
    k_main<<<MSTEPS / 256, 256>>>((float*)d_out);
}

// round 9
// speedup vs baseline: 2.6267x; 1.0779x over previous
#include <cuda_runtime.h>
#include <math.h>
#include <limits.h>

#define NMESH  256
#define MSTEPS 4096
#define SLEN   (MSTEPS + 1)     // scan steps 0..M (step 0 = pseudo init sweep-up at hc=1.0)
#define SLENP  4128             // padded to multiple of 32 (129 chunks)
#define NCH    (SLENP / 32)     // 129
#define TRI    (NMESH * (NMESH + 1) / 2)
#define SENTD  32767
#define CHUNK  8
#define ILPAD  4112             // SLEN padded to multiple of 4 for uint4 copy
#define NBLK   17
#define TPB    1024

// ---------------- device scratch ----------------
__device__ float  g_P[TRI];                   // per-row inclusive prefix of softplus density
__device__ float  g_rowsum[NMESH];
__device__ int    g_il[ILPAD];                // packed: (iu:9)<<22 | (link+1:13)<<9 | (segMin+1:9)
__device__ int    g_start[SLEN];              // packed: lastup<<9 | (dminLast+1)
__device__ float  g_A[NMESH + 1];             // prefix of rowsums; g_A[NMESH] = S
__device__ float  g_colpreT[NMESH * NMESH];   // colpreT[k*N+j] = sum_{r=j..k} P_r(j)

// grid barrier state (generation-based; persists across graph replays)
__device__ volatile int g_bar_count = 0;
__device__ volatile int g_bar_gen   = 0;

__device__ __forceinline__ void grid_barrier() {
    __syncthreads();
    if (threadIdx.x == 0) {
        int gen = g_bar_gen;
        __threadfence();
        if (atomicAdd((int*)&g_bar_count, 1) == NBLK - 1) {
            g_bar_count = 0;
            __threadfence();
            g_bar_gen = gen + 1;
        } else {
            while (g_bar_gen == gen) __nanosleep(32);
        }
        __threadfence();
    }
    __syncthreads();
}

__device__ __forceinline__ float softplusf(float x) {
    return fmaxf(x, 0.f) + log1pf(expf(-fabsf(x)));
}

// shared-memory overlay: meta arrays (block 16) / walk arrays (phase 3, all blocks)
union SMem {
    struct {
        float lin[NMESH];
        short s_iu[SLENP];
        short s_d[SLENP];
        short s_lu[SLENP];
        short pmind[SLENP];   // prefix-min of d within each 32-chunk
        short smind[SLENP];   // suffix-min of d within each 32-chunk
        short cmind[NCH];     // chunk min of d
        short cmaxu[NCH];     // chunk max of iu
        int   sc[32];
    } meta;
    struct {
        int   s_il[ILPAD];
        float s_A[NMESH + 1];
    } walk;
};

__global__ void __launch_bounds__(TPB, 1) k_fused(const float* __restrict__ h,
                                                  const float* __restrict__ raw,
                                                  const float* __restrict__ m2,
                                                  const float* __restrict__ m3,
                                                  float* __restrict__ out) {
    __shared__ SMem sm;
    int tid = threadIdx.x, b = blockIdx.x;
    int lane = tid & 31, w = tid >> 5;
    int gw = b * 32 + w;             // global warp id among blocks 0-15 (0..511)

    // ================= Phase 1 =================
    if (b == 16) {
        // ---- meta part A: lin, classification, lastup ----
        if (tid < NMESH) {
            const float* xx = (m2[1] != m2[0]) ? m2 : m3;
            sm.meta.lin[tid] = xx[tid];
        }
        __syncthreads();

        for (int s = tid; s < SLENP; s += TPB) {
            short iu = 0, dd = (short)SENTD;
            if (s < SLEN) {
                float hc, hp;
                if (s == 0) { hc = 1.0f; hp = h[MSTEPS - 1]; }
                else { hc = h[s - 1]; hp = (s == 1) ? 1.0f : h[s - 2]; }
                if (hc > hp) {             // sweep up: rows with alpha < hc reset full
                    int lo = 0, hi = NMESH;
                    while (lo < hi) { int m = (lo + hi) >> 1; if (sm.meta.lin[m] < hc) lo = m + 1; else hi = m; }
                    iu = (short)lo;
                } else if (hc < hp) {      // sweep down: clamp c to max j with beta_j <= hc
                    int lo = 0, hi = NMESH;
                    while (lo < hi) { int m = (lo + hi) >> 1; if (sm.meta.lin[m] <= hc) lo = m + 1; else hi = m; }
                    dd = (short)(lo - 1);
                }
            }
            sm.meta.s_iu[s] = iu; sm.meta.s_d[s] = dd;
        }
        __syncthreads();

        // lastup: inclusive max-scan of (up ? s : -1)
        {
            int base = tid * 4;
            int w0 = (sm.meta.s_iu[base]     > 0) ? base     : -1;
            int w1 = (sm.meta.s_iu[base + 1] > 0) ? base + 1 : -1;
            int w2 = (sm.meta.s_iu[base + 2] > 0) ? base + 2 : -1;
            int w3 = (sm.meta.s_iu[base + 3] > 0) ? base + 3 : -1;
            int l0 = w0, l1 = max(l0, w1), l2 = max(l1, w2), l3 = max(l2, w3);
            int v = l3;
#pragma unroll
            for (int o = 1; o < 32; o <<= 1) { int u = __shfl_up_sync(0xffffffffu, v, o); if (lane >= o) v = max(v, u); }
            if (lane == 31) sm.meta.sc[w] = v;
            __syncthreads();
            if (w == 0) {
                int x = sm.meta.sc[lane];
#pragma unroll
                for (int o = 1; o < 32; o <<= 1) { int u = __shfl_up_sync(0xffffffffu, x, o); if (lane >= o) x = max(x, u); }
                sm.meta.sc[lane] = x;
            }
            __syncthreads();
            int warppre = (w > 0) ? sm.meta.sc[w - 1] : INT_MIN;
            int lanepre = __shfl_up_sync(0xffffffffu, v, 1);
            int pre = (lane == 0) ? warppre : max(warppre, lanepre);
            sm.meta.s_lu[base]     = (short)max(pre, l0);
            sm.meta.s_lu[base + 1] = (short)max(pre, l1);
            sm.meta.s_lu[base + 2] = (short)max(pre, l2);
            sm.meta.s_lu[base + 3] = (short)max(pre, l3);
            if (tid == TPB - 1) {
                int w4 = (sm.meta.s_iu[4096] > 0) ? 4096 : -1;
                sm.meta.s_lu[4096] = (short)max(max(pre, l3), w4);
            }
        }
        __syncthreads();

        // per-chunk prefix/suffix min of d, chunk min d, chunk max iu
        for (int c = w; c < NCH; c += 32) {
            int e = c * 32 + lane;
            int dv = sm.meta.s_d[e];
            int uv = sm.meta.s_iu[e];
            int p = dv;
#pragma unroll
            for (int o = 1; o < 32; o <<= 1) { int u = __shfl_up_sync(0xffffffffu, p, o); if (lane >= o) p = min(p, u); }
            sm.meta.pmind[e] = (short)p;
            int q = dv;
#pragma unroll
            for (int o = 1; o < 32; o <<= 1) { int u = __shfl_down_sync(0xffffffffu, q, o); if (lane + o < 32) q = min(q, u); }
            sm.meta.smind[e] = (short)q;
            if (lane == 31) sm.meta.cmind[c] = (short)p;
            int m = uv;
#pragma unroll
            for (int o = 16; o >= 1; o >>= 1) m = max(m, __shfl_xor_sync(0xffffffffu, m, o));
            if (lane == 0) sm.meta.cmaxu[c] = (short)m;
        }
        __syncthreads();
    } else {
        // ---- rowprefix: one warp per row, segmented warp scan ----
        int r = gw;
        if (r < NMESH) {
            int off = r * (r + 1) / 2;
            float carry = 0.f;
            int nseg = (r >> 5) + 1;
            for (int seg = 0; seg < nseg; seg++) {
                int idx = seg * 32 + lane;
                float v = (idx <= r) ? softplusf(raw[off + idx]) : 0.f;
#pragma unroll
                for (int o = 1; o < 32; o <<= 1) { float u = __shfl_up_sync(0xffffffffu, v, o); if (lane >= o) v += u; }
                v += carry;
                if (idx <= r) g_P[off + idx] = v;
                carry = __shfl_sync(0xffffffffu, v, 31);
            }
            if (lane == 0) g_rowsum[r] = carry;
        }
    }

    grid_barrier();

    // ================= Phase 2 =================
    if (b == 16) {
        // ---- meta part B: PGE link + segMin -> g_il; lastup RMQ -> g_start ----
        for (int s = tid; s < SLEN; s += TPB) {
            int iu = sm.meta.s_iu[s];
            int lnk = -1;
            int e = 257;                              // segMin+1 encoding; 257 = +inf
            if (iu > 0 && iu < NMESH - 1) {
                // PGE: rightmost s' < s with iu[s'] > iu (step 0 has iu=255, terminates)
                int i = s - 1;
                int c = i >> 5;
                int found = -1;
                for (; i >= (c << 5); i--) if ((int)sm.meta.s_iu[i] > iu) { found = i; break; }
                if (found < 0) {
                    for (c = c - 1; (int)sm.meta.cmaxu[c] <= iu; c--) {}
                    for (i = (c << 5) + 31; ; i--) if ((int)sm.meta.s_iu[i] > iu) { found = i; break; }
                }
                lnk = found;
                // segMin d over [lnk+1, s]
                int l = lnk + 1, r = s;
                int cl = l >> 5, cr = r >> 5;
                int v;
                if (cl == cr) {
                    v = SENTD;
                    for (int ii = l; ii <= r; ii++) v = min(v, (int)sm.meta.s_d[ii]);
                } else {
                    v = min((int)sm.meta.smind[l], (int)sm.meta.pmind[r]);
                    for (int cc = cl + 1; cc < cr; cc++) v = min(v, (int)sm.meta.cmind[cc]);
                }
                e = min(v + 1, 257);
            }
            g_il[s] = (iu << 22) | ((lnk + 1) << 9) | e;

            // g_start: lastup + min d over (lastup, s]
            int lu = sm.meta.s_lu[s];
            int enc = 257;
            if (lu < s) {
                int l = lu + 1, r = s;
                int cl = l >> 5, cr = r >> 5;
                int v;
                if (cl == cr) {
                    v = SENTD;
                    for (int ii = l; ii <= r; ii++) v = min(v, (int)sm.meta.s_d[ii]);
                } else {
                    v = min((int)sm.meta.smind[l], (int)sm.meta.pmind[r]);
                    for (int cc = cl + 1; cc < cr; cc++) v = min(v, (int)sm.meta.cmind[cc]);
                }
                enc = min(v + 1, 257);
            }
            g_start[s] = (lu << 9) | enc;
        }
        if (tid < ILPAD - SLEN) g_il[SLEN + tid] = 0;   // zero uint4 padding tail
    } else {
        // ---- colpreT: one warp per column, segmented warp scan over k ----
        int j = gw;
        if (j < NMESH) {
            float carry = 0.f;
            for (int seg = j >> 5; seg < 8; seg++) {
                int k = seg * 32 + lane;
                float v = (k >= j) ? g_P[k * (k + 1) / 2 + j] : 0.f;
#pragma unroll
                for (int o = 1; o < 32; o <<= 1) { float u = __shfl_up_sync(0xffffffffu, v, o); if (lane >= o) v += u; }
                v += carry;
                if (k >= j) g_colpreT[k * NMESH + j] = v;
                carry = __shfl_sync(0xffffffffu, v, 31);
            }
        } else if (j == NMESH) {
            // A prefix of rowsums
            float carry = 0.f;
            for (int seg = 0; seg < 8; seg++) {
                int k = seg * 32 + lane;
                float v = g_rowsum[k];
#pragma unroll
                for (int o = 1; o < 32; o <<= 1) { float u = __shfl_up_sync(0xffffffffu, v, o); if (lane >= o) v += u; }
                v += carry;
                g_A[k + 1] = v;
                carry = __shfl_sync(0xffffffffu, v, 31);
            }
            if (lane == 0) g_A[0] = 0.f;
        }
    }

    grid_barrier();

    // ================= Phase 3: chain walk (all blocks) =================
    // consecutive t per block -> correlated chain lengths within warps
    int t = b * 241 + tid;                 // 17*241 = 4097 >= 4096
    bool active = (tid < 241) && (t < MSTEPS);
    int T = t + 1;
    int st = active ? g_start[T] : 0;      // issue early

    {
        const uint4* src = (const uint4*)g_il;
        uint4* dst = (uint4*)sm.walk.s_il;
        for (int i = tid; i < ILPAD / 4; i += TPB) dst[i] = src[i];
        for (int i = tid; i <= NMESH; i += TPB) sm.walk.s_A[i] = g_A[i];
    }
    __syncthreads();
    if (!active) return;

    int s = st >> 9;
    int Vmin = (st & 0x1FF) - 1;    // 256 acts as +inf
    int lo = 0;
    float acc = 0.f;
    bool finished = false;

    while (!finished) {
        // ---- Phase A: LDS-only chase; record (lo, hi, V) per level ----
        int hiA[CHUNK], VA[CHUNK], loA[CHUNK];
        bool act[CHUNK];
        bool done = false;
#pragma unroll
        for (int c = 0; c < CHUNK; c++) {
            act[c] = !done;
            if (!done) {
                int il = sm.walk.s_il[s];
                int hi = (unsigned)il >> 22;
                hiA[c] = hi; VA[c] = Vmin; loA[c] = lo;
                if (hi >= NMESH - 1) done = true;
                else {
                    Vmin = min(Vmin, (il & 0x1FF) - 1);
                    s = ((il >> 9) & 0x1FFF) - 1;
                    lo = hi;
                }
            } else { hiA[c] = 0; VA[c] = -1; loA[c] = 0; }
        }

        // ---- Phase B: batched independent colpre/A accumulation ----
        float a0 = 0.f, a1 = 0.f, a2 = 0.f, a3 = 0.f;
#pragma unroll
        for (int c = 0; c < CHUNK; c++) {
            float contrib = 0.f;
            if (act[c]) {
                int hi = hiA[c], V = VA[c], lol = loA[c];
                if (V >= hi - 1) {
                    contrib = sm.walk.s_A[hi] - sm.walk.s_A[lol];
                } else if (V >= 0) {
                    int m = max(lol, V + 1);
                    contrib = sm.walk.s_A[m] - sm.walk.s_A[lol]
                            + g_colpreT[(hi - 1) * NMESH + V]
                            - g_colpreT[(m - 1) * NMESH + V];
                }
            }
            if ((c & 3) == 0) a0 += contrib;
            else if ((c & 3) == 1) a1 += contrib;
            else if ((c & 3) == 2) a2 += contrib;
            else a3 += contrib;
        }
        acc += (a0 + a1) + (a2 + a3);
        finished = done;
    }

    float S = sm.walk.s_A[NMESH];
    out[t] = (2.f * acc - S) / S;
}

// ---------------- launch: single fused kernel ----------------
extern "C" void kernel_launch(void* const* d_in, const int* in_sizes, int n_in,
                              void* d_out, int out_size) {
    const float* h   = nullptr;
    const float* raw = nullptr;
    const float* m2  = nullptr;
    const float* m3  = nullptr;
    for (int i = 0; i < n_in; i++) {
        if (in_sizes[i] == MSTEPS && !h)            h   = (const float*)d_in[i];
        else if (in_sizes[i] == TRI && !raw)        raw = (const float*)d_in[i];
        else if (in_sizes[i] == NMESH * NMESH) {
            if (!m2) m2 = (const float*)d_in[i];
            else     m3 = (const float*)d_in[i];
        }
    }
    if (!m3) m3 = m2;

    k_fused<<<NBLK, TPB>>>(h, raw, m2, m3, (float*)d_out);
}

// round 10
// speedup vs baseline: 2.9953x; 1.1404x over previous
#include <cuda_runtime.h>
#include <math.h>
#include <limits.h>

#define NMESH  256
#define MSTEPS 4096
#define SLEN   (MSTEPS + 1)     // scan steps 0..M (step 0 = pseudo init sweep-up at hc=1.0)
#define SLENP  4128             // padded to multiple of 32 (129 chunks)
#define NCH    (SLENP / 32)     // 129
#define NCHP   136              // padded to multiple of 8 shorts (16B)
#define TRI    (NMESH * (NMESH + 1) / 2)
#define SENTD  32767
#define CHUNK  8
#define ILPAD  4112             // SLEN padded to multiple of 4 for uint4 copy
#define NBLK   17
#define TPB    1024

// ---------------- device scratch ----------------
__device__ float  g_P[TRI];                   // per-row inclusive prefix of softplus density
__device__ float  g_rowsum[NMESH];
__device__ int    g_il[ILPAD];                // packed: (iu:9)<<22 | (link+1:13)<<9 | (segMin+1:9)
__device__ int    g_start[SLEN];              // packed: lastup<<13... actually lastup<<9 | (dminLast+1)
__device__ float  g_A[NMESH + 1];             // prefix of rowsums; g_A[NMESH] = S
__device__ float  g_colpreT[NMESH * NMESH];   // colpreT[k*N+j] = sum_{r=j..k} P_r(j)
// published meta tables (block 16 -> all blocks)
__device__ short  g_iu16[SLENP];
__device__ short  g_d16[SLENP];
__device__ short  g_lu16[SLENP];
__device__ short  g_pm[SLENP];                // per-chunk prefix-min of d
__device__ short  g_sm[SLENP];                // per-chunk suffix-min of d
__device__ short  g_cmin[NCHP];               // chunk min of d
__device__ short  g_cmax[NCHP];               // chunk max of iu

// grid barrier state (generation-based; persists across graph replays)
__device__ volatile int g_bar_count = 0;
__device__ volatile int g_bar_gen   = 0;

__device__ __forceinline__ void grid_barrier() {
    __syncthreads();
    if (threadIdx.x == 0) {
        int gen = g_bar_gen;
        __threadfence();
        if (atomicAdd((int*)&g_bar_count, 1) == NBLK - 1) {
            g_bar_count = 0;
            __threadfence();
            g_bar_gen = gen + 1;
        } else {
            while (g_bar_gen == gen) __nanosleep(32);
        }
        __threadfence();
    }
    __syncthreads();
}

__device__ __forceinline__ float softplusf(float x) {
    return fmaxf(x, 0.f) + log1pf(expf(-fabsf(x)));
}

// shared-memory overlay
union SMem {
    struct {   // phase 1, block 16
        float lin[NMESH];
        short s_iu[SLENP];
        short s_d[SLENP];
        short s_lu[SLENP];
        short pmind[SLENP];
        short smind[SLENP];
        short cmind[NCHP];
        short cmaxu[NCHP];
        int   sc[32];
    } meta;
    struct {   // phase 2, all blocks (part B scan arrays)
        short p_iu[SLENP];
        short p_d[SLENP];
        short p_cmind[NCHP];
        short p_cmaxu[NCHP];
    } pb;
    struct {   // phase 3, blocks 0-3
        int   s_il[ILPAD];
        float s_A[NMESH + 1];
    } walk;
};

__global__ void __launch_bounds__(TPB, 1) k_fused(const float* __restrict__ h,
                                                  const float* __restrict__ raw,
                                                  const float* __restrict__ m2,
                                                  const float* __restrict__ m3,
                                                  float* __restrict__ out) {
    __shared__ SMem sm;
    int tid = threadIdx.x, b = blockIdx.x;
    int lane = tid & 31, w = tid >> 5;

    // ================= Phase 1 =================
    if (b == 16) {
        // ---- meta part A: lin, classification, lastup, chunk mins; publish ----
        if (tid < NMESH) {
            const float* xx = (m2[1] != m2[0]) ? m2 : m3;
            sm.meta.lin[tid] = xx[tid];
        }
        __syncthreads();

        for (int s = tid; s < SLENP; s += TPB) {
            short iu = 0, dd = (short)SENTD;
            if (s < SLEN) {
                float hc, hp;
                if (s == 0) { hc = 1.0f; hp = h[MSTEPS - 1]; }
                else { hc = h[s - 1]; hp = (s == 1) ? 1.0f : h[s - 2]; }
                if (hc > hp) {             // sweep up
                    int lo = 0, hi = NMESH;
                    while (lo < hi) { int m = (lo + hi) >> 1; if (sm.meta.lin[m] < hc) lo = m + 1; else hi = m; }
                    iu = (short)lo;
                } else if (hc < hp) {      // sweep down
                    int lo = 0, hi = NMESH;
                    while (lo < hi) { int m = (lo + hi) >> 1; if (sm.meta.lin[m] <= hc) lo = m + 1; else hi = m; }
                    dd = (short)(lo - 1);
                }
            }
            sm.meta.s_iu[s] = iu; sm.meta.s_d[s] = dd;
        }
        __syncthreads();

        // lastup: inclusive max-scan of (up ? s : -1)
        {
            int base = tid * 4;
            int w0 = (sm.meta.s_iu[base]     > 0) ? base     : -1;
            int w1 = (sm.meta.s_iu[base + 1] > 0) ? base + 1 : -1;
            int w2 = (sm.meta.s_iu[base + 2] > 0) ? base + 2 : -1;
            int w3 = (sm.meta.s_iu[base + 3] > 0) ? base + 3 : -1;
            int l0 = w0, l1 = max(l0, w1), l2 = max(l1, w2), l3 = max(l2, w3);
            int v = l3;
#pragma unroll
            for (int o = 1; o < 32; o <<= 1) { int u = __shfl_up_sync(0xffffffffu, v, o); if (lane >= o) v = max(v, u); }
            if (lane == 31) sm.meta.sc[w] = v;
            __syncthreads();
            if (w == 0) {
                int x = sm.meta.sc[lane];
#pragma unroll
                for (int o = 1; o < 32; o <<= 1) { int u = __shfl_up_sync(0xffffffffu, x, o); if (lane >= o) x = max(x, u); }
                sm.meta.sc[lane] = x;
            }
            __syncthreads();
            int warppre = (w > 0) ? sm.meta.sc[w - 1] : INT_MIN;
            int lanepre = __shfl_up_sync(0xffffffffu, v, 1);
            int pre = (lane == 0) ? warppre : max(warppre, lanepre);
            sm.meta.s_lu[base]     = (short)max(pre, l0);
            sm.meta.s_lu[base + 1] = (short)max(pre, l1);
            sm.meta.s_lu[base + 2] = (short)max(pre, l2);
            sm.meta.s_lu[base + 3] = (short)max(pre, l3);
            if (tid == TPB - 1) {
                int w4 = (sm.meta.s_iu[4096] > 0) ? 4096 : -1;
                sm.meta.s_lu[4096] = (short)max(max(pre, l3), w4);
            }
        }
        __syncthreads();

        // per-chunk prefix/suffix min of d, chunk min d, chunk max iu
        for (int c = w; c < NCH; c += 32) {
            int e = c * 32 + lane;
            int dv = sm.meta.s_d[e];
            int uv = sm.meta.s_iu[e];
            int p = dv;
#pragma unroll
            for (int o = 1; o < 32; o <<= 1) { int u = __shfl_up_sync(0xffffffffu, p, o); if (lane >= o) p = min(p, u); }
            sm.meta.pmind[e] = (short)p;
            int q = dv;
#pragma unroll
            for (int o = 1; o < 32; o <<= 1) { int u = __shfl_down_sync(0xffffffffu, q, o); if (lane + o < 32) q = min(q, u); }
            sm.meta.smind[e] = (short)q;
            if (lane == 31) sm.meta.cmind[c] = (short)p;
            int m = uv;
#pragma unroll
            for (int o = 16; o >= 1; o >>= 1) m = max(m, __shfl_xor_sync(0xffffffffu, m, o));
            if (lane == 0) sm.meta.cmaxu[c] = (short)m;
        }
        __syncthreads();

        // publish tables to global
        for (int i = tid; i < SLENP; i += TPB) {
            g_iu16[i] = sm.meta.s_iu[i];
            g_d16[i]  = sm.meta.s_d[i];
            g_lu16[i] = sm.meta.s_lu[i];
            g_pm[i]   = sm.meta.pmind[i];
            g_sm[i]   = sm.meta.smind[i];
        }
        if (tid < NCH) { g_cmin[tid] = sm.meta.cmind[tid]; g_cmax[tid] = sm.meta.cmaxu[tid]; }
        else if (tid < NCHP) { g_cmin[tid] = (short)SENTD; g_cmax[tid] = -1; }
    } else {
        // ---- rowprefix: one warp per row, segment loads hoisted ----
        int r = b * 32 + w;
        if (r < NMESH) {
            int off = r * (r + 1) / 2;
            float v[8];
#pragma unroll
            for (int seg = 0; seg < 8; seg++) {
                int idx = seg * 32 + lane;
                v[seg] = (idx <= r) ? raw[off + idx] : 0.f;   // independent loads
            }
#pragma unroll
            for (int seg = 0; seg < 8; seg++) {
                int idx = seg * 32 + lane;
                v[seg] = (idx <= r) ? softplusf(v[seg]) : 0.f;
            }
            float carry = 0.f;
#pragma unroll
            for (int seg = 0; seg < 8; seg++) {
                if (seg * 32 <= r) {       // warp-uniform
                    float x = v[seg];
#pragma unroll
                    for (int o = 1; o < 32; o <<= 1) { float u = __shfl_up_sync(0xffffffffu, x, o); if (lane >= o) x += u; }
                    x += carry;
                    int idx = seg * 32 + lane;
                    if (idx <= r) g_P[off + idx] = x;
                    carry = __shfl_sync(0xffffffffu, x, 31);
                }
            }
            if (lane == 0) g_rowsum[r] = carry;
        }
    }

    grid_barrier();

    // ================= Phase 2 =================
    // copy part-B scan tables into every block's smem (16B loads)
    {
        const uint4* a0 = (const uint4*)g_iu16;
        const uint4* a1 = (const uint4*)g_d16;
        uint4* d0 = (uint4*)sm.pb.p_iu;
        uint4* d1 = (uint4*)sm.pb.p_d;
        for (int i = tid; i < SLENP / 8; i += TPB) { d0[i] = a0[i]; d1[i] = a1[i]; }
        if (tid < NCHP / 8) {
            ((uint4*)sm.pb.p_cmind)[tid] = ((const uint4*)g_cmin)[tid];
            ((uint4*)sm.pb.p_cmaxu)[tid] = ((const uint4*)g_cmax)[tid];
        }
        if (b == 0 && tid < ILPAD - SLEN) g_il[SLEN + tid] = 0;   // zero padding tail
    }
    __syncthreads();

    if (w < 16) {
        // ---- colpreT / A-prefix: one warp per column, segment loads hoisted ----
        int j = b * 16 + w;
        if (j < NMESH) {
            float v[8];
#pragma unroll
            for (int seg = 0; seg < 8; seg++) {
                int k = seg * 32 + lane;
                v[seg] = (k >= j) ? g_P[k * (k + 1) / 2 + j] : 0.f;
            }
            float carry = 0.f;
#pragma unroll
            for (int seg = 0; seg < 8; seg++) {
                float x = v[seg];
#pragma unroll
                for (int o = 1; o < 32; o <<= 1) { float u = __shfl_up_sync(0xffffffffu, x, o); if (lane >= o) x += u; }
                x += carry;
                int k = seg * 32 + lane;
                if (k >= j) g_colpreT[k * NMESH + j] = x;
                carry = __shfl_sync(0xffffffffu, x, 31);
            }
        } else if (j == NMESH) {
            float v[8];
#pragma unroll
            for (int seg = 0; seg < 8; seg++) v[seg] = g_rowsum[seg * 32 + lane];
            float carry = 0.f;
#pragma unroll
            for (int seg = 0; seg < 8; seg++) {
                float x = v[seg];
#pragma unroll
                for (int o = 1; o < 32; o <<= 1) { float u = __shfl_up_sync(0xffffffffu, x, o); if (lane >= o) x += u; }
                x += carry;
                g_A[seg * 32 + lane + 1] = x;
                carry = __shfl_sync(0xffffffffu, x, 31);
            }
            if (lane == 0) g_A[0] = 0.f;
        }
    } else {
        // ---- meta part B (spread): each thread handles at most one s ----
        int k = tid - 512;
        int s = b * 241 + k;
        if (k < 241 && s < SLEN) {
            int iu = sm.pb.p_iu[s];
            int lnk = -1;
            int e = 257;                              // segMin+1 encoding; 257 = +inf
            if (iu > 0 && iu < NMESH - 1) {
                // PGE: rightmost s' < s with iu[s'] > iu (step 0 has iu=255, terminates)
                int i = s - 1;
                int c = i >> 5;
                int found = -1;
                for (; i >= (c << 5); i--) if ((int)sm.pb.p_iu[i] > iu) { found = i; break; }
                if (found < 0) {
                    for (c = c - 1; (int)sm.pb.p_cmaxu[c] <= iu; c--) {}
                    for (i = (c << 5) + 31; ; i--) if ((int)sm.pb.p_iu[i] > iu) { found = i; break; }
                }
                lnk = found;
                // segMin d over [lnk+1, s]
                int l = lnk + 1, r = s;
                int cl = l >> 5, cr = r >> 5;
                int v;
                if (cl == cr) {
                    v = SENTD;
                    for (int ii = l; ii <= r; ii++) v = min(v, (int)sm.pb.p_d[ii]);
                } else {
                    v = min((int)g_sm[l], (int)g_pm[r]);
                    for (int cc = cl + 1; cc < cr; cc++) v = min(v, (int)sm.pb.p_cmind[cc]);
                }
                e = min(v + 1, 257);
            }
            g_il[s] = (iu << 22) | ((lnk + 1) << 9) | e;

            // g_start: lastup + min d over (lastup, s]
            int lu = g_lu16[s];
            int enc = 257;
            if (lu < s) {
                int l = lu + 1, r = s;
                int cl = l >> 5, cr = r >> 5;
                int v;
                if (cl == cr) {
                    v = SENTD;
                    for (int ii = l; ii <= r; ii++) v = min(v, (int)sm.pb.p_d[ii]);
                } else {
                    v = min((int)g_sm[l], (int)g_pm[r]);
                    for (int cc = cl + 1; cc < cr; cc++) v = min(v, (int)sm.pb.p_cmind[cc]);
                }
                enc = min(v + 1, 257);
            }
            g_start[s] = (lu << 9) | enc;
        }
    }

    grid_barrier();

    // ================= Phase 3: chain walk (blocks 0-3, fully active) =================
    if (b >= 4) return;

    int t = b * TPB + tid;                 // 4*1024 = 4096 outputs
    int T = t + 1;
    int st = g_start[T];                   // issue early

    {
        const uint4* src = (const uint4*)g_il;
        uint4* dst = (uint4*)sm.walk.s_il;
        for (int i = tid; i < ILPAD / 4; i += TPB) dst[i] = src[i];
        for (int i = tid; i <= NMESH; i += TPB) sm.walk.s_A[i] = g_A[i];
    }
    __syncthreads();

    int s = st >> 9;
    int Vmin = (st & 0x1FF) - 1;    // 256 acts as +inf
    int lo = 0;
    float acc = 0.f;
    bool finished = false;

    while (!finished) {
        // ---- Phase A: LDS-only chase; record (lo, hi, V) per level ----
        int hiA[CHUNK], VA[CHUNK], loA[CHUNK];
        bool act[CHUNK];
        bool done = false;
#pragma unroll
        for (int c = 0; c < CHUNK; c++) {
            act[c] = !done;
            if (!done) {
                int il = sm.walk.s_il[s];
                int hi = (unsigned)il >> 22;
                hiA[c] = hi; VA[c] = Vmin; loA[c] = lo;
                if (hi >= NMESH - 1) done = true;
                else {
                    Vmin = min(Vmin, (il & 0x1FF) - 1);
                    s = ((il >> 9) & 0x1FFF) - 1;
                    lo = hi;
                }
            } else { hiA[c] = 0; VA[c] = -1; loA[c] = 0; }
        }

        // ---- Phase B: batched independent colpre/A accumulation ----
        float a0 = 0.f, a1 = 0.f, a2 = 0.f, a3 = 0.f;
#pragma unroll
        for (int c = 0; c < CHUNK; c++) {
            float contrib = 0.f;
            if (act[c]) {
                int hi = hiA[c], V = VA[c], lol = loA[c];
                if (V >= hi - 1) {
                    contrib = sm.walk.s_A[hi] - sm.walk.s_A[lol];
                } else if (V >= 0) {
                    int m = max(lol, V + 1);
                    contrib = sm.walk.s_A[m] - sm.walk.s_A[lol]
                            + g_colpreT[(hi - 1) * NMESH + V]
                            - g_colpreT[(m - 1) * NMESH + V];
                }
            }
            if ((c & 3) == 0) a0 += contrib;
            else if ((c & 3) == 1) a1 += contrib;
            else if ((c & 3) == 2) a2 += contrib;
            else a3 += contrib;
        }
        acc += (a0 + a1) + (a2 + a3);
        finished = done;
    }

    float S = sm.walk.s_A[NMESH];
    out[t] = (2.f * acc - S) / S;
}

// ---------------- launch: single fused kernel ----------------
extern "C" void kernel_launch(void* const* d_in, const int* in_sizes, int n_in,
                              void* d_out, int out_size) {
    const float* h   = nullptr;
    const float* raw = nullptr;
    const float* m2  = nullptr;
    const float* m3  = nullptr;
    for (int i = 0; i < n_in; i++) {
        if (in_sizes[i] == MSTEPS && !h)            h   = (const float*)d_in[i];
        else if (in_sizes[i] == TRI && !raw)        raw = (const float*)d_in[i];
        else if (in_sizes[i] == NMESH * NMESH) {
            if (!m2) m2 = (const float*)d_in[i];
            else     m3 = (const float*)d_in[i];
        }
    }
    if (!m3) m3 = m2;

    k_fused<<<NBLK, TPB>>>(h, raw, m2, m3, (float*)d_out);
}

// round 11
// speedup vs baseline: 3.0488x; 1.0179x over previous
#include <cuda_runtime.h>
#include <math.h>
#include <limits.h>

#define NMESH  256
#define MSTEPS 4096
#define SLEN   (MSTEPS + 1)     // scan steps 0..M (step 0 = pseudo init sweep-up at hc=1.0)
#define SLENP  4128             // padded to multiple of 32 (129 chunks)
#define NCH    (SLENP / 32)     // 129
#define NCHP   136              // padded to multiple of 8 shorts (16B)
#define TRI    (NMESH * (NMESH + 1) / 2)
#define SENTD  32767
#define CHUNK  8
#define ILPAD  4112             // SLEN padded to multiple of 4 for uint4 copy
#define NBLK   32
#define TPB    1024

// ---------------- device scratch ----------------
__device__ float  g_P[TRI];                   // per-row inclusive prefix of softplus density
__device__ float  g_rowsum[NMESH];
__device__ int    g_il[ILPAD];                // packed: (iu:9)<<22 | (link+1:13)<<9 | (segMin+1:9)
__device__ int    g_start[SLEN];              // packed: lastup<<9 | (dminLast+1)
__device__ float  g_A[NMESH + 1];             // prefix of rowsums; g_A[NMESH] = S
__device__ float  g_colpreT[NMESH * NMESH];   // colpreT[k*N+j] = sum_{r=j..k} P_r(j)
// published meta tables (block 16 -> partB blocks)
__device__ short  g_iu16[SLENP];
__device__ short  g_d16[SLENP];
__device__ short  g_lu16[SLENP];
__device__ short  g_pm[SLENP];                // per-chunk prefix-min of d
__device__ short  g_sm[SLENP];                // per-chunk suffix-min of d
__device__ short  g_cmin[NCHP];               // chunk min of d
__device__ short  g_cmax[NCHP];               // chunk max of iu

// grid barrier state (generation-based; persists across graph replays)
__device__ volatile int g_bar_count = 0;
__device__ volatile int g_bar_gen   = 0;

__device__ __forceinline__ void grid_barrier() {
    __syncthreads();
    if (threadIdx.x == 0) {
        int gen = g_bar_gen;
        __threadfence();
        if (atomicAdd((int*)&g_bar_count, 1) == NBLK - 1) {
            g_bar_count = 0;
            __threadfence();
            g_bar_gen = gen + 1;
        } else {
            while (g_bar_gen == gen) __nanosleep(32);
        }
        __threadfence();
    }
    __syncthreads();
}

__device__ __forceinline__ float softplusf(float x) {
    return fmaxf(x, 0.f) + log1pf(expf(-fabsf(x)));
}

// shared-memory overlay
union SMem {
    struct {   // phase 1, block 16
        float lin[NMESH];
        short s_iu[SLENP];
        short s_d[SLENP];
        short s_lu[SLENP];
        short pmind[SLENP];
        short smind[SLENP];
        short cmind[NCHP];
        short cmaxu[NCHP];
        int   sc[32];
    } meta;
    struct {   // phase 2, partB blocks (16..31)
        short p_iu[SLENP];
        short p_d[SLENP];
        short p_cmind[NCHP];
        short p_cmaxu[NCHP];
    } pb;
    struct {   // phase 3, all blocks
        int   s_il[ILPAD];
        float s_A[NMESH + 1];
    } walk;
};

__global__ void __launch_bounds__(TPB, 1) k_fused(const float* __restrict__ h,
                                                  const float* __restrict__ raw,
                                                  const float* __restrict__ m2,
                                                  const float* __restrict__ m3,
                                                  float* __restrict__ out) {
    __shared__ SMem sm;
    int tid = threadIdx.x, b = blockIdx.x;
    int lane = tid & 31, w = tid >> 5;

    // ================= Phase 1 =================
    if (b == 16) {
        // ---- meta part A: lin, classification, lastup, chunk mins; publish ----
        if (tid < NMESH) {
            const float* xx = (m2[1] != m2[0]) ? m2 : m3;
            sm.meta.lin[tid] = xx[tid];
        }
        __syncthreads();

        for (int s = tid; s < SLENP; s += TPB) {
            short iu = 0, dd = (short)SENTD;
            if (s < SLEN) {
                float hc, hp;
                if (s == 0) { hc = 1.0f; hp = h[MSTEPS - 1]; }
                else { hc = h[s - 1]; hp = (s == 1) ? 1.0f : h[s - 2]; }
                if (hc > hp) {             // sweep up
                    int lo = 0, hi = NMESH;
                    while (lo < hi) { int m = (lo + hi) >> 1; if (sm.meta.lin[m] < hc) lo = m + 1; else hi = m; }
                    iu = (short)lo;
                } else if (hc < hp) {      // sweep down
                    int lo = 0, hi = NMESH;
                    while (lo < hi) { int m = (lo + hi) >> 1; if (sm.meta.lin[m] <= hc) lo = m + 1; else hi = m; }
                    dd = (short)(lo - 1);
                }
            }
            sm.meta.s_iu[s] = iu; sm.meta.s_d[s] = dd;
        }
        __syncthreads();

        // lastup: inclusive max-scan of (up ? s : -1)
        {
            int base = tid * 4;
            int w0 = (sm.meta.s_iu[base]     > 0) ? base     : -1;
            int w1 = (sm.meta.s_iu[base + 1] > 0) ? base + 1 : -1;
            int w2 = (sm.meta.s_iu[base + 2] > 0) ? base + 2 : -1;
            int w3 = (sm.meta.s_iu[base + 3] > 0) ? base + 3 : -1;
            int l0 = w0, l1 = max(l0, w1), l2 = max(l1, w2), l3 = max(l2, w3);
            int v = l3;
#pragma unroll
            for (int o = 1; o < 32; o <<= 1) { int u = __shfl_up_sync(0xffffffffu, v, o); if (lane >= o) v = max(v, u); }
            if (lane == 31) sm.meta.sc[w] = v;
            __syncthreads();
            if (w == 0) {
                int x = sm.meta.sc[lane];
#pragma unroll
                for (int o = 1; o < 32; o <<= 1) { int u = __shfl_up_sync(0xffffffffu, x, o); if (lane >= o) x = max(x, u); }
                sm.meta.sc[lane] = x;
            }
            __syncthreads();
            int warppre = (w > 0) ? sm.meta.sc[w - 1] : INT_MIN;
            int lanepre = __shfl_up_sync(0xffffffffu, v, 1);
            int pre = (lane == 0) ? warppre : max(warppre, lanepre);
            sm.meta.s_lu[base]     = (short)max(pre, l0);
            sm.meta.s_lu[base + 1] = (short)max(pre, l1);
            sm.meta.s_lu[base + 2] = (short)max(pre, l2);
            sm.meta.s_lu[base + 3] = (short)max(pre, l3);
            if (tid == TPB - 1) {
                int w4 = (sm.meta.s_iu[4096] > 0) ? 4096 : -1;
                sm.meta.s_lu[4096] = (short)max(max(pre, l3), w4);
            }
        }
        __syncthreads();

        // per-chunk prefix/suffix min of d, chunk min d, chunk max iu
        for (int c = w; c < NCH; c += 32) {
            int e = c * 32 + lane;
            int dv = sm.meta.s_d[e];
            int uv = sm.meta.s_iu[e];
            int p = dv;
#pragma unroll
            for (int o = 1; o < 32; o <<= 1) { int u = __shfl_up_sync(0xffffffffu, p, o); if (lane >= o) p = min(p, u); }
            sm.meta.pmind[e] = (short)p;
            int q = dv;
#pragma unroll
            for (int o = 1; o < 32; o <<= 1) { int u = __shfl_down_sync(0xffffffffu, q, o); if (lane + o < 32) q = min(q, u); }
            sm.meta.smind[e] = (short)q;
            if (lane == 31) sm.meta.cmind[c] = (short)p;
            int m = uv;
#pragma unroll
            for (int o = 16; o >= 1; o >>= 1) m = max(m, __shfl_xor_sync(0xffffffffu, m, o));
            if (lane == 0) sm.meta.cmaxu[c] = (short)m;
        }
        __syncthreads();

        // publish tables to global
        for (int i = tid; i < SLENP; i += TPB) {
            g_iu16[i] = sm.meta.s_iu[i];
            g_d16[i]  = sm.meta.s_d[i];
            g_lu16[i] = sm.meta.s_lu[i];
            g_pm[i]   = sm.meta.pmind[i];
            g_sm[i]   = sm.meta.smind[i];
        }
        if (tid < NCH) { g_cmin[tid] = sm.meta.cmind[tid]; g_cmax[tid] = sm.meta.cmaxu[tid]; }
        else if (tid < NCHP) { g_cmin[tid] = (short)SENTD; g_cmax[tid] = -1; }
    } else if (b < 8) {
        // ---- rowprefix: one warp per row (blocks 0-7), segment loads hoisted ----
        int r = b * 32 + w;
        {
            int off = r * (r + 1) / 2;
            float v[8];
#pragma unroll
            for (int seg = 0; seg < 8; seg++) {
                int idx = seg * 32 + lane;
                v[seg] = (idx <= r) ? raw[off + idx] : 0.f;   // independent loads
            }
#pragma unroll
            for (int seg = 0; seg < 8; seg++) {
                int idx = seg * 32 + lane;
                v[seg] = (idx <= r) ? softplusf(v[seg]) : 0.f;
            }
            float carry = 0.f;
#pragma unroll
            for (int seg = 0; seg < 8; seg++) {
                if (seg * 32 <= r) {       // warp-uniform
                    float x = v[seg];
#pragma unroll
                    for (int o = 1; o < 32; o <<= 1) { float u = __shfl_up_sync(0xffffffffu, x, o); if (lane >= o) x += u; }
                    x += carry;
                    int idx = seg * 32 + lane;
                    if (idx <= r) g_P[off + idx] = x;
                    carry = __shfl_sync(0xffffffffu, x, 31);
                }
            }
            if (lane == 0) g_rowsum[r] = carry;
        }
    }

    grid_barrier();

    // ================= Phase 2 =================
    if (b >= 16) {
        // copy part-B scan tables into smem (16B loads)
        {
            const uint4* a0 = (const uint4*)g_iu16;
            const uint4* a1 = (const uint4*)g_d16;
            uint4* d0 = (uint4*)sm.pb.p_iu;
            uint4* d1 = (uint4*)sm.pb.p_d;
            for (int i = tid; i < SLENP / 8; i += TPB) { d0[i] = a0[i]; d1[i] = a1[i]; }
            if (tid < NCHP / 8) {
                ((uint4*)sm.pb.p_cmind)[tid] = ((const uint4*)g_cmin)[tid];
                ((uint4*)sm.pb.p_cmaxu)[tid] = ((const uint4*)g_cmax)[tid];
            }
            if (b == 16 && tid >= 512 && tid < 512 + (ILPAD - SLEN)) g_il[SLEN + (tid - 512)] = 0;
        }
        __syncthreads();

        // ---- meta part B: each of blocks 16..31 handles 257 s-values ----
        int s = (b - 16) * 257 + tid;
        if (tid < 257 && s < SLEN) {
            int iu = sm.pb.p_iu[s];
            int lnk = -1;
            int e = 257;                              // segMin+1 encoding; 257 = +inf
            if (iu > 0 && iu < NMESH - 1) {
                // PGE: rightmost s' < s with iu[s'] > iu (step 0 has iu=255, terminates)
                int i = s - 1;
                int c = i >> 5;
                int found = -1;
                for (; i >= (c << 5); i--) if ((int)sm.pb.p_iu[i] > iu) { found = i; break; }
                if (found < 0) {
                    for (c = c - 1; (int)sm.pb.p_cmaxu[c] <= iu; c--) {}
                    for (i = (c << 5) + 31; ; i--) if ((int)sm.pb.p_iu[i] > iu) { found = i; break; }
                }
                lnk = found;
                // segMin d over [lnk+1, s]
                int l = lnk + 1, r = s;
                int cl = l >> 5, cr = r >> 5;
                int v;
                if (cl == cr) {
                    v = SENTD;
                    for (int ii = l; ii <= r; ii++) v = min(v, (int)sm.pb.p_d[ii]);
                } else {
                    v = min((int)g_sm[l], (int)g_pm[r]);
                    for (int cc = cl + 1; cc < cr; cc++) v = min(v, (int)sm.pb.p_cmind[cc]);
                }
                e = min(v + 1, 257);
            }
            g_il[s] = (iu << 22) | ((lnk + 1) << 9) | e;

            // g_start: lastup + min d over (lastup, s]
            int lu = g_lu16[s];
            int enc = 257;
            if (lu < s) {
                int l = lu + 1, r = s;
                int cl = l >> 5, cr = r >> 5;
                int v;
                if (cl == cr) {
                    v = SENTD;
                    for (int ii = l; ii <= r; ii++) v = min(v, (int)sm.pb.p_d[ii]);
                } else {
                    v = min((int)g_sm[l], (int)g_pm[r]);
                    for (int cc = cl + 1; cc < cr; cc++) v = min(v, (int)sm.pb.p_cmind[cc]);
                }
                enc = min(v + 1, 257);
            }
            g_start[s] = (lu << 9) | enc;
        }
    } else if (b < 9) {
        // ---- colpreT / A-prefix: one warp per column (blocks 0-8), loads hoisted ----
        int j = b * 32 + w;
        if (j < NMESH) {
            float v[8];
#pragma unroll
            for (int seg = 0; seg < 8; seg++) {
                int k = seg * 32 + lane;
                v[seg] = (k >= j) ? g_P[k * (k + 1) / 2 + j] : 0.f;
            }
            float carry = 0.f;
#pragma unroll
            for (int seg = 0; seg < 8; seg++) {
                float x = v[seg];
#pragma unroll
                for (int o = 1; o < 32; o <<= 1) { float u = __shfl_up_sync(0xffffffffu, x, o); if (lane >= o) x += u; }
                x += carry;
                int k = seg * 32 + lane;
                if (k >= j) g_colpreT[k * NMESH + j] = x;
                carry = __shfl_sync(0xffffffffu, x, 31);
            }
        } else if (j == NMESH) {
            float v[8];
#pragma unroll
            for (int seg = 0; seg < 8; seg++) v[seg] = g_rowsum[seg * 32 + lane];
            float carry = 0.f;
#pragma unroll
            for (int seg = 0; seg < 8; seg++) {
                float x = v[seg];
#pragma unroll
                for (int o = 1; o < 32; o <<= 1) { float u = __shfl_up_sync(0xffffffffu, x, o); if (lane >= o) x += u; }
                x += carry;
                g_A[seg * 32 + lane + 1] = x;
                carry = __shfl_sync(0xffffffffu, x, 31);
            }
            if (lane == 0) g_A[0] = 0.f;
        }
    }

    grid_barrier();

    // ================= Phase 3: chain walk (all 32 blocks, 128 outputs each) ===========
    int t = b * 128 + tid;                 // 32*128 = 4096 outputs
    bool active = (tid < 128);
    int T = t + 1;
    int st = active ? g_start[T] : 0;      // issue early

    {
        const uint4* src = (const uint4*)g_il;
        uint4* dst = (uint4*)sm.walk.s_il;
        for (int i = tid; i < ILPAD / 4; i += TPB) dst[i] = src[i];
        for (int i = tid; i <= NMESH; i += TPB) sm.walk.s_A[i] = g_A[i];
    }
    __syncthreads();
    if (!active) return;

    int s = st >> 9;
    int Vmin = (st & 0x1FF) - 1;    // 256 acts as +inf
    int lo = 0;
    float acc = 0.f;
    bool finished = false;

    while (!finished) {
        // ---- Phase A: LDS-only chase; record (lo, hi, V) per level ----
        int hiA[CHUNK], VA[CHUNK], loA[CHUNK];
        bool act[CHUNK];
        bool done = false;
#pragma unroll
        for (int c = 0; c < CHUNK; c++) {
            act[c] = !done;
            if (!done) {
                int il = sm.walk.s_il[s];
                int hi = (unsigned)il >> 22;
                hiA[c] = hi; VA[c] = Vmin; loA[c] = lo;
                if (hi >= NMESH - 1) done = true;
                else {
                    Vmin = min(Vmin, (il & 0x1FF) - 1);
                    s = ((il >> 9) & 0x1FFF) - 1;
                    lo = hi;
                }
            } else { hiA[c] = 0; VA[c] = -1; loA[c] = 0; }
        }

        // ---- Phase B: batched independent colpre/A accumulation ----
        float a0 = 0.f, a1 = 0.f, a2 = 0.f, a3 = 0.f;
#pragma unroll
        for (int c = 0; c < CHUNK; c++) {
            float contrib = 0.f;
            if (act[c]) {
                int hi = hiA[c], V = VA[c], lol = loA[c];
                if (V >= hi - 1) {
                    contrib = sm.walk.s_A[hi] - sm.walk.s_A[lol];
                } else if (V >= 0) {
                    int m = max(lol, V + 1);
                    contrib = sm.walk.s_A[m] - sm.walk.s_A[lol]
                            + g_colpreT[(hi - 1) * NMESH + V]
                            - g_colpreT[(m - 1) * NMESH + V];
                }
            }
            if ((c & 3) == 0) a0 += contrib;
            else if ((c & 3) == 1) a1 += contrib;
            else if ((c & 3) == 2) a2 += contrib;
            else a3 += contrib;
        }
        acc += (a0 + a1) + (a2 + a3);
        finished = done;
    }

    float S = sm.walk.s_A[NMESH];
    out[t] = (2.f * acc - S) / S;
}

// ---------------- launch: single fused kernel ----------------
extern "C" void kernel_launch(void* const* d_in, const int* in_sizes, int n_in,
                              void* d_out, int out_size) {
    const float* h   = nullptr;
    const float* raw = nullptr;
    const float* m2  = nullptr;
    const float* m3  = nullptr;
    for (int i = 0; i < n_in; i++) {
        if (in_sizes[i] == MSTEPS && !h)            h   = (const float*)d_in[i];
        else if (in_sizes[i] == TRI && !raw)        raw = (const float*)d_in[i];
        else if (in_sizes[i] == NMESH * NMESH) {
            if (!m2) m2 = (const float*)d_in[i];
            else     m3 = (const float*)d_in[i];
        }
    }
    if (!m3) m3 = m2;

    k_fused<<<NBLK, TPB>>>(h, raw, m2, m3, (float*)d_out);
}

// round 12
// speedup vs baseline: 3.9040x; 1.2805x over previous
#include <cuda_runtime.h>
#include <math.h>
#include <limits.h>

#define NMESH  256
#define MSTEPS 4096
#define SLEN   (MSTEPS + 1)     // scan steps 0..M (step 0 = pseudo init sweep-up at hc=1.0)
#define SLENP  4128             // padded to multiple of 32 (129 chunks)
#define NCH    (SLENP / 32)     // 129
#define NCHP   136
#define TRI    (NMESH * (NMESH + 1) / 2)
#define SENTD  32767
#define CHUNK  8
#define ILPAD  4112             // SLEN padded to multiple of 4 for uint4 copy
#define NBLK   32
#define TPB    1024

// ---------------- device scratch ----------------
__device__ float  g_P[TRI];                   // per-row inclusive prefix of softplus density
__device__ float  g_rowsum[NMESH];
__device__ int    g_il[ILPAD];                // packed: (iu:9)<<22 | (link+1:13)<<9 | (segMin+1:9)
__device__ int    g_start[SLEN];              // packed: lastup<<9 | (dminLast+1)
__device__ float  g_A[NMESH + 1];             // prefix of rowsums; g_A[NMESH] = S
__device__ float  g_colpreT[NMESH * NMESH];   // colpreT[k*N+j] = sum_{r=j..k} P_r(j)

// barriers (generation-based; persist across graph replays)
__device__ volatile int g_bar_count = 0, g_bar_gen = 0;   // full (32 blocks)
__device__ volatile int g_sub_count = 0, g_sub_gen = 0;   // rows group (16 blocks)

__device__ __forceinline__ void barrier_n(volatile int* cnt, volatile int* gen, int target) {
    __syncthreads();
    if (threadIdx.x == 0) {
        int g = *gen;
        __threadfence();
        if (atomicAdd((int*)cnt, 1) == target - 1) {
            *cnt = 0;
            __threadfence();
            *gen = g + 1;
        } else {
            while (*gen == g) __nanosleep(32);
        }
        __threadfence();
    }
    __syncthreads();
}

__device__ __forceinline__ float softplusf(float x) {
    return fmaxf(x, 0.f) + log1pf(expf(-fabsf(x)));
}

// shared-memory overlay
union SMem {
    struct {   // phase 1-2, blocks 16-31 (redundant metaA + local partB)
        float lin[NMESH];
        short s_iu[SLENP];
        short s_d[SLENP];
        short s_lu[SLENP];
        short pmind[SLENP];
        short smind[SLENP];
        short cmind[NCHP];
        short cmaxu[NCHP];
        int   sc[32];
    } meta;
    struct {   // phase 3, all blocks
        int   s_il[ILPAD];
        float s_A[NMESH + 1];
    } walk;
};

// range-min of d over [l, r] using chunk tables (all smem, unrolled in-chunk)
__device__ __forceinline__ int rmin_d(const short* s_d, const short* pmind,
                                      const short* smind, const short* cmind,
                                      int l, int r) {
    int cl = l >> 5, cr = r >> 5;
    if (cl == cr) {
        int v = SENTD;
        int base = cl << 5;
#pragma unroll
        for (int ii = 0; ii < 32; ii++) {
            int idx = base + ii;
            int dv = s_d[idx];                    // independent LDS
            if (idx >= l && idx <= r) v = min(v, dv);
        }
        return v;
    }
    int v = min((int)smind[l], (int)pmind[r]);
    for (int cc = cl + 1; cc < cr; cc++) v = min(v, (int)cmind[cc]);
    return v;
}

__global__ void __launch_bounds__(TPB, 1) k_fused(const float* __restrict__ h,
                                                  const float* __restrict__ raw,
                                                  const float* __restrict__ m2,
                                                  const float* __restrict__ m3,
                                                  float* __restrict__ out) {
    __shared__ SMem sm;
    int tid = threadIdx.x, b = blockIdx.x;
    int lane = tid & 31, w = tid >> 5;

    if (b >= 16) {
        // ============ meta pipeline (blocks 16-31, fully local) ============
        if (tid < NMESH) {
            const float* xx = (m2[1] != m2[0]) ? m2 : m3;
            sm.meta.lin[tid] = xx[tid];
        }
        __syncthreads();

        // ---- classification: arithmetic candidate + exact fixup on mesh floats ----
        for (int s = tid; s < SLENP; s += TPB) {
            short iu = 0, dd = (short)SENTD;
            if (s < SLEN) {
                float hc, hp;
                if (s == 0) { hc = 1.0f; hp = h[MSTEPS - 1]; }
                else { hc = h[s - 1]; hp = (s == 1) ? 1.0f : h[s - 2]; }
                if (hc > hp) {
                    // lo = first m with lin[m] >= hc
                    int m = (int)((hc + 1.0f) * 127.5f);
                    m = min(max(m, 0), 255);
                    while (m > 0 && sm.meta.lin[m - 1] >= hc) m--;
                    while (m < 256 && sm.meta.lin[m] < hc) m++;
                    iu = (short)m;
                } else if (hc < hp) {
                    // dd = (first m with lin[m] > hc) - 1
                    int m = (int)((hc + 1.0f) * 127.5f);
                    m = min(max(m, 0), 255);
                    while (m > 0 && sm.meta.lin[m - 1] > hc) m--;
                    while (m < 256 && sm.meta.lin[m] <= hc) m++;
                    dd = (short)(m - 1);
                }
            }
            sm.meta.s_iu[s] = iu; sm.meta.s_d[s] = dd;
        }
        __syncthreads();

        // ---- lastup: inclusive max-scan of (up ? s : -1) ----
        {
            int base = tid * 4;
            int w0 = (sm.meta.s_iu[base]     > 0) ? base     : -1;
            int w1 = (sm.meta.s_iu[base + 1] > 0) ? base + 1 : -1;
            int w2 = (sm.meta.s_iu[base + 2] > 0) ? base + 2 : -1;
            int w3 = (sm.meta.s_iu[base + 3] > 0) ? base + 3 : -1;
            int l0 = w0, l1 = max(l0, w1), l2 = max(l1, w2), l3 = max(l2, w3);
            int v = l3;
#pragma unroll
            for (int o = 1; o < 32; o <<= 1) { int u = __shfl_up_sync(0xffffffffu, v, o); if (lane >= o) v = max(v, u); }
            if (lane == 31) sm.meta.sc[w] = v;
            __syncthreads();
            if (w == 0) {
                int x = sm.meta.sc[lane];
#pragma unroll
                for (int o = 1; o < 32; o <<= 1) { int u = __shfl_up_sync(0xffffffffu, x, o); if (lane >= o) x = max(x, u); }
                sm.meta.sc[lane] = x;
            }
            __syncthreads();
            int warppre = (w > 0) ? sm.meta.sc[w - 1] : INT_MIN;
            int lanepre = __shfl_up_sync(0xffffffffu, v, 1);
            int pre = (lane == 0) ? warppre : max(warppre, lanepre);
            sm.meta.s_lu[base]     = (short)max(pre, l0);
            sm.meta.s_lu[base + 1] = (short)max(pre, l1);
            sm.meta.s_lu[base + 2] = (short)max(pre, l2);
            sm.meta.s_lu[base + 3] = (short)max(pre, l3);
            if (tid == TPB - 1) {
                int w4 = (sm.meta.s_iu[4096] > 0) ? 4096 : -1;
                sm.meta.s_lu[4096] = (short)max(max(pre, l3), w4);
            }
        }
        __syncthreads();

        // ---- per-chunk prefix/suffix min of d, chunk min d, chunk max iu ----
        for (int c = w; c < NCH; c += 32) {
            int e = c * 32 + lane;
            int dv = sm.meta.s_d[e];
            int uv = sm.meta.s_iu[e];
            int p = dv;
#pragma unroll
            for (int o = 1; o < 32; o <<= 1) { int u = __shfl_up_sync(0xffffffffu, p, o); if (lane >= o) p = min(p, u); }
            sm.meta.pmind[e] = (short)p;
            int q = dv;
#pragma unroll
            for (int o = 1; o < 32; o <<= 1) { int u = __shfl_down_sync(0xffffffffu, q, o); if (lane + o < 32) q = min(q, u); }
            sm.meta.smind[e] = (short)q;
            if (lane == 31) sm.meta.cmind[c] = (short)p;
            int m = uv;
#pragma unroll
            for (int o = 16; o >= 1; o >>= 1) m = max(m, __shfl_xor_sync(0xffffffffu, m, o));
            if (lane == 0) sm.meta.cmaxu[c] = (short)m;
        }
        __syncthreads();

        // ---- partB: each block handles 257 s-values from its local tables ----
        {
            int s = (b - 16) * 257 + tid;
            if (tid < 257 && s < SLEN) {
                int iu = sm.meta.s_iu[s];
                int lnk = -1;
                int e = 257;                              // segMin+1 encoding; 257 = +inf
                if (iu > 0 && iu < NMESH - 1) {
                    // PGE: rightmost s' < s with iu[s'] > iu (unrolled independent LDS)
                    int ci = (s - 1) >> 5;
                    int base = ci << 5;
                    int found = -1;
#pragma unroll
                    for (int ii = 0; ii < 32; ii++) {
                        int idx = base + ii;
                        int val = sm.meta.s_iu[idx];
                        if (idx < s && val > iu) found = idx;
                    }
                    if (found < 0) {
                        int c = ci - 1;
                        while ((int)sm.meta.cmaxu[c] <= iu) c--;
                        base = c << 5;
#pragma unroll
                        for (int ii = 0; ii < 32; ii++) {
                            int idx = base + ii;
                            int val = sm.meta.s_iu[idx];
                            if (val > iu) found = idx;
                        }
                    }
                    lnk = found;
                    int v = rmin_d(sm.meta.s_d, sm.meta.pmind, sm.meta.smind, sm.meta.cmind, lnk + 1, s);
                    e = min(v + 1, 257);
                }
                g_il[s] = (iu << 22) | ((lnk + 1) << 9) | e;

                // g_start: lastup + min d over (lastup, s]
                int lu = sm.meta.s_lu[s];
                int enc = 257;
                if (lu < s) {
                    int v = rmin_d(sm.meta.s_d, sm.meta.pmind, sm.meta.smind, sm.meta.cmind, lu + 1, s);
                    enc = min(v + 1, 257);
                }
                g_start[s] = (lu << 9) | enc;
            }
            if (b == 16 && tid >= 512 && tid < 512 + (ILPAD - SLEN)) g_il[SLEN + (tid - 512)] = 0;
        }
    } else {
        // ============ density pipeline (blocks 0-15) ============
        // ---- rowprefix: rows r = b*16 + w (w<16), segment loads hoisted ----
        if (w < 16) {
            int r = b * 16 + w;
            int off = r * (r + 1) / 2;
            float v[8];
#pragma unroll
            for (int seg = 0; seg < 8; seg++) {
                int idx = seg * 32 + lane;
                v[seg] = (idx <= r) ? raw[off + idx] : 0.f;   // independent loads
            }
#pragma unroll
            for (int seg = 0; seg < 8; seg++) {
                int idx = seg * 32 + lane;
                v[seg] = (idx <= r) ? softplusf(v[seg]) : 0.f;
            }
            float carry = 0.f;
#pragma unroll
            for (int seg = 0; seg < 8; seg++) {
                if (seg * 32 <= r) {       // warp-uniform
                    float x = v[seg];
#pragma unroll
                    for (int o = 1; o < 32; o <<= 1) { float u = __shfl_up_sync(0xffffffffu, x, o); if (lane >= o) x += u; }
                    x += carry;
                    int idx = seg * 32 + lane;
                    if (idx <= r) g_P[off + idx] = x;
                    carry = __shfl_sync(0xffffffffu, x, 31);
                }
            }
            if (lane == 0) g_rowsum[r] = carry;
        }

        barrier_n(&g_sub_count, &g_sub_gen, 16);   // rowprefix -> colpre (blocks 0-15 only)

        // ---- colpreT / A-prefix: one warp per column (blocks 0-8) ----
        int j = b * 32 + w;
        if (j < NMESH) {
            float v[8];
#pragma unroll
            for (int seg = 0; seg < 8; seg++) {
                int k = seg * 32 + lane;
                v[seg] = (k >= j) ? g_P[k * (k + 1) / 2 + j] : 0.f;
            }
            float carry = 0.f;
#pragma unroll
            for (int seg = 0; seg < 8; seg++) {
                float x = v[seg];
#pragma unroll
                for (int o = 1; o < 32; o <<= 1) { float u = __shfl_up_sync(0xffffffffu, x, o); if (lane >= o) x += u; }
                x += carry;
                int k = seg * 32 + lane;
                if (k >= j) g_colpreT[k * NMESH + j] = x;
                carry = __shfl_sync(0xffffffffu, x, 31);
            }
        } else if (j == NMESH) {
            float v[8];
#pragma unroll
            for (int seg = 0; seg < 8; seg++) v[seg] = g_rowsum[seg * 32 + lane];
            float carry = 0.f;
#pragma unroll
            for (int seg = 0; seg < 8; seg++) {
                float x = v[seg];
#pragma unroll
                for (int o = 1; o < 32; o <<= 1) { float u = __shfl_up_sync(0xffffffffu, x, o); if (lane >= o) x += u; }
                x += carry;
                g_A[seg * 32 + lane + 1] = x;
                carry = __shfl_sync(0xffffffffu, x, 31);
            }
            if (lane == 0) g_A[0] = 0.f;
        }
    }

    barrier_n(&g_bar_count, &g_bar_gen, NBLK);     // everything -> P3

    // ================= Phase 3: chain walk (all 32 blocks, 128 outputs each) ===========
    int t = b * 128 + tid;                 // 32*128 = 4096 outputs
    bool active = (tid < 128);
    int T = t + 1;
    int st = active ? g_start[T] : 0;      // issue early

    {
        const uint4* src = (const uint4*)g_il;
        uint4* dst = (uint4*)sm.walk.s_il;
        for (int i = tid; i < ILPAD / 4; i += TPB) dst[i] = src[i];
        for (int i = tid; i <= NMESH; i += TPB) sm.walk.s_A[i] = g_A[i];
    }
    __syncthreads();
    if (!active) return;

    int s = st >> 9;
    int Vmin = (st & 0x1FF) - 1;    // 256 acts as +inf
    int lo = 0;
    float acc = 0.f;
    bool finished = false;

    while (!finished) {
        // ---- Phase A: LDS-only chase; record (lo, hi, V) per level ----
        int hiA[CHUNK], VA[CHUNK], loA[CHUNK];
        bool act[CHUNK];
        bool done = false;
#pragma unroll
        for (int c = 0; c < CHUNK; c++) {
            act[c] = !done;
            if (!done) {
                int il = sm.walk.s_il[s];
                int hi = (unsigned)il >> 22;
                hiA[c] = hi; VA[c] = Vmin; loA[c] = lo;
                if (hi >= NMESH - 1) done = true;
                else {
                    Vmin = min(Vmin, (il & 0x1FF) - 1);
                    s = ((il >> 9) & 0x1FFF) - 1;
                    lo = hi;
                }
            } else { hiA[c] = 0; VA[c] = -1; loA[c] = 0; }
        }

        // ---- Phase B: batched independent colpre/A accumulation ----
        float a0 = 0.f, a1 = 0.f, a2 = 0.f, a3 = 0.f;
#pragma unroll
        for (int c = 0; c < CHUNK; c++) {
            float contrib = 0.f;
            if (act[c]) {
                int hi = hiA[c], V = VA[c], lol = loA[c];
                if (V >= hi - 1) {
                    contrib = sm.walk.s_A[hi] - sm.walk.s_A[lol];
                } else if (V >= 0) {
                    int m = max(lol, V + 1);
                    contrib = sm.walk.s_A[m] - sm.walk.s_A[lol]
                            + g_colpreT[(hi - 1) * NMESH + V]
                            - g_colpreT[(m - 1) * NMESH + V];
                }
            }
            if ((c & 3) == 0) a0 += contrib;
            else if ((c & 3) == 1) a1 += contrib;
            else if ((c & 3) == 2) a2 += contrib;
            else a3 += contrib;
        }
        acc += (a0 + a1) + (a2 + a3);
        finished = done;
    }

    float S = sm.walk.s_A[NMESH];
    out[t] = (2.f * acc - S) / S;
}

// ---------------- launch: single fused kernel ----------------
extern "C" void kernel_launch(void* const* d_in, const int* in_sizes, int n_in,
                              void* d_out, int out_size) {
    const float* h   = nullptr;
    const float* raw = nullptr;
    const float* m2  = nullptr;
    const float* m3  = nullptr;
    for (int i = 0; i < n_in; i++) {
        if (in_sizes[i] == MSTEPS && !h)            h   = (const float*)d_in[i];
        else if (in_sizes[i] == TRI && !raw)        raw = (const float*)d_in[i];
        else if (in_sizes[i] == NMESH * NMESH) {
            if (!m2) m2 = (const float*)d_in[i];
            else     m3 = (const float*)d_in[i];
        }
    }
    if (!m3) m3 = m2;

    k_fused<<<NBLK, TPB>>>(h, raw, m2, m3, (float*)d_out);
}

// round 13
// speedup vs baseline: 4.8504x; 1.2424x over previous
#include <cuda_runtime.h>
#include <math.h>
#include <limits.h>

#define NMESH  256
#define MSTEPS 4096
#define SLEN   (MSTEPS + 1)     // scan steps 0..M (step 0 = pseudo init sweep-up at hc=1.0)
#define SLENP  4128             // padded to multiple of 32 (129 chunks)
#define NCH    (SLENP / 32)     // 129
#define NCHP   136
#define TRI    (NMESH * (NMESH + 1) / 2)
#define SENTD  32767
#define CHUNK  8
#define ILPAD  4112             // SLEN padded to multiple of 4 for uint4 copy
#define NBLK   32
#define TPB    1024

// ---------------- device scratch ----------------
__device__ float  g_P[TRI];                   // per-row inclusive prefix of softplus density
__device__ float  g_rowsum[NMESH];
__device__ int    g_il[ILPAD];                // packed: (iu:9)<<22 | (link+1:13)<<9 | (segMin+1:9)
__device__ int    g_start[SLEN];              // packed: lastup<<9 | (dminLast+1)
__device__ float  g_A[NMESH + 1];             // prefix of rowsums; g_A[NMESH] = S
__device__ float  g_colpreT[NMESH * NMESH];   // colpreT[k*N+j] = sum_{r=j..k} P_r(j)

// barriers (generation-based; persist across graph replays)
__device__ volatile int g_bar_count = 0, g_bar_gen = 0;   // full (32 blocks)
__device__ volatile int g_sub_count = 0, g_sub_gen = 0;   // density group (16 blocks)

__device__ __forceinline__ void barrier_n(volatile int* cnt, volatile int* gen, int target) {
    __syncthreads();
    if (threadIdx.x == 0) {
        int g = *gen;
        __threadfence();
        if (atomicAdd((int*)cnt, 1) == target - 1) {
            *cnt = 0;
            __threadfence();
            *gen = g + 1;
        } else {
            while (*gen == g) __nanosleep(32);
        }
        __threadfence();
    }
    __syncthreads();
}

__device__ __forceinline__ float softplusf(float x) {
    return fmaxf(x, 0.f) + log1pf(expf(-fabsf(x)));
}

// shared-memory overlay
union SMem {
    struct {   // meta pipeline, blocks 16-31 (redundant metaA + local partB)
        float lin[NMESH];
        short s_iu[SLENP];
        short s_d[SLENP];
        short s_lu[SLENP];
        short pmind[SLENP];
        short smind[SLENP];
        short cmind[NCHP];
        short cmaxu[NCHP];
        int   sc[32];
    } meta;
    struct {   // colpre tile, blocks 0-7
        float tile[NMESH * 33];   // padded stride 33 -> conflict-free column access
    } cp;
    struct {   // phase 3, all blocks
        int   s_il[ILPAD];
        float s_A[NMESH + 1];
    } walk;
};

// range-min of d over [l, r] using chunk tables (all smem, unrolled in-chunk)
__device__ __forceinline__ int rmin_d(const short* s_d, const short* pmind,
                                      const short* smind, const short* cmind,
                                      int l, int r) {
    int cl = l >> 5, cr = r >> 5;
    if (cl == cr) {
        int v = SENTD;
        int base = cl << 5;
#pragma unroll
        for (int ii = 0; ii < 32; ii++) {
            int idx = base + ii;
            int dv = s_d[idx];                    // independent LDS
            if (idx >= l && idx <= r) v = min(v, dv);
        }
        return v;
    }
    int v = min((int)smind[l], (int)pmind[r]);
    for (int cc = cl + 1; cc < cr; cc++) v = min(v, (int)cmind[cc]);
    return v;
}

__global__ void __launch_bounds__(TPB, 1) k_fused(const float* __restrict__ h,
                                                  const float* __restrict__ raw,
                                                  const float* __restrict__ m2,
                                                  const float* __restrict__ m3,
                                                  float* __restrict__ out) {
    __shared__ SMem sm;
    int tid = threadIdx.x, b = blockIdx.x;
    int lane = tid & 31, w = tid >> 5;

    if (b >= 16) {
        // ============ meta pipeline (blocks 16-31, fully local) ============
        if (tid < NMESH) {
            const float* xx = (m2[1] != m2[0]) ? m2 : m3;
            sm.meta.lin[tid] = xx[tid];
        }
        __syncthreads();

        // ---- classification: arithmetic candidate + exact fixup on mesh floats ----
        for (int s = tid; s < SLENP; s += TPB) {
            short iu = 0, dd = (short)SENTD;
            if (s < SLEN) {
                float hc, hp;
                if (s == 0) { hc = 1.0f; hp = h[MSTEPS - 1]; }
                else { hc = h[s - 1]; hp = (s == 1) ? 1.0f : h[s - 2]; }
                if (hc > hp) {
                    int m = (int)((hc + 1.0f) * 127.5f);
                    m = min(max(m, 0), 255);
                    while (m > 0 && sm.meta.lin[m - 1] >= hc) m--;
                    while (m < 256 && sm.meta.lin[m] < hc) m++;
                    iu = (short)m;
                } else if (hc < hp) {
                    int m = (int)((hc + 1.0f) * 127.5f);
                    m = min(max(m, 0), 255);
                    while (m > 0 && sm.meta.lin[m - 1] > hc) m--;
                    while (m < 256 && sm.meta.lin[m] <= hc) m++;
                    dd = (short)(m - 1);
                }
            }
            sm.meta.s_iu[s] = iu; sm.meta.s_d[s] = dd;
        }
        __syncthreads();

        // ---- lastup local + chunk mins fused (one barrier serves both) ----
        int v_lu;
        int l0, l1, l2, l3;
        {
            int base = tid * 4;
            int w0 = (sm.meta.s_iu[base]     > 0) ? base     : -1;
            int w1 = (sm.meta.s_iu[base + 1] > 0) ? base + 1 : -1;
            int w2 = (sm.meta.s_iu[base + 2] > 0) ? base + 2 : -1;
            int w3 = (sm.meta.s_iu[base + 3] > 0) ? base + 3 : -1;
            l0 = w0; l1 = max(l0, w1); l2 = max(l1, w2); l3 = max(l2, w3);
            v_lu = l3;
#pragma unroll
            for (int o = 1; o < 32; o <<= 1) { int u = __shfl_up_sync(0xffffffffu, v_lu, o); if (lane >= o) v_lu = max(v_lu, u); }
            if (lane == 31) sm.meta.sc[w] = v_lu;
        }
        // chunk mins (independent of lastup scan; reads s_iu/s_d only)
        for (int c = w; c < NCH; c += 32) {
            int e = c * 32 + lane;
            int dv = sm.meta.s_d[e];
            int uv = sm.meta.s_iu[e];
            int p = dv;
#pragma unroll
            for (int o = 1; o < 32; o <<= 1) { int u = __shfl_up_sync(0xffffffffu, p, o); if (lane >= o) p = min(p, u); }
            sm.meta.pmind[e] = (short)p;
            int q = dv;
#pragma unroll
            for (int o = 1; o < 32; o <<= 1) { int u = __shfl_down_sync(0xffffffffu, q, o); if (lane + o < 32) q = min(q, u); }
            sm.meta.smind[e] = (short)q;
            if (lane == 31) sm.meta.cmind[c] = (short)p;
            int m = uv;
#pragma unroll
            for (int o = 16; o >= 1; o >>= 1) m = max(m, __shfl_xor_sync(0xffffffffu, m, o));
            if (lane == 0) sm.meta.cmaxu[c] = (short)m;
        }
        __syncthreads();
        if (w == 0) {
            int x = sm.meta.sc[lane];
#pragma unroll
            for (int o = 1; o < 32; o <<= 1) { int u = __shfl_up_sync(0xffffffffu, x, o); if (lane >= o) x = max(x, u); }
            sm.meta.sc[lane] = x;
        }
        __syncthreads();
        {
            int base = tid * 4;
            int warppre = (w > 0) ? sm.meta.sc[w - 1] : INT_MIN;
            int lanepre = __shfl_up_sync(0xffffffffu, v_lu, 1);
            int pre = (lane == 0) ? warppre : max(warppre, lanepre);
            sm.meta.s_lu[base]     = (short)max(pre, l0);
            sm.meta.s_lu[base + 1] = (short)max(pre, l1);
            sm.meta.s_lu[base + 2] = (short)max(pre, l2);
            sm.meta.s_lu[base + 3] = (short)max(pre, l3);
            if (tid == TPB - 1) {
                int w4 = (sm.meta.s_iu[4096] > 0) ? 4096 : -1;
                sm.meta.s_lu[4096] = (short)max(max(pre, l3), w4);
            }
        }
        __syncthreads();

        // ---- partB: each block handles 257 s-values from its local tables ----
        {
            int s = (b - 16) * 257 + tid;
            if (tid < 257 && s < SLEN) {
                int iu = sm.meta.s_iu[s];
                int lnk = -1;
                int e = 257;                              // segMin+1 encoding; 257 = +inf
                if (iu > 0 && iu < NMESH - 1) {
                    // PGE: rightmost s' < s with iu[s'] > iu (unrolled independent LDS)
                    int ci = (s - 1) >> 5;
                    int base = ci << 5;
                    int found = -1;
#pragma unroll
                    for (int ii = 0; ii < 32; ii++) {
                        int idx = base + ii;
                        int val = sm.meta.s_iu[idx];
                        if (idx < s && val > iu) found = idx;
                    }
                    if (found < 0) {
                        int c = ci - 1;
                        while ((int)sm.meta.cmaxu[c] <= iu) c--;
                        base = c << 5;
#pragma unroll
                        for (int ii = 0; ii < 32; ii++) {
                            int idx = base + ii;
                            int val = sm.meta.s_iu[idx];
                            if (val > iu) found = idx;
                        }
                    }
                    lnk = found;
                    int v = rmin_d(sm.meta.s_d, sm.meta.pmind, sm.meta.smind, sm.meta.cmind, lnk + 1, s);
                    e = min(v + 1, 257);
                }
                g_il[s] = (iu << 22) | ((lnk + 1) << 9) | e;

                // g_start: lastup + min d over (lastup, s]
                int lu = sm.meta.s_lu[s];
                int enc = 257;
                if (lu < s) {
                    int v = rmin_d(sm.meta.s_d, sm.meta.pmind, sm.meta.smind, sm.meta.cmind, lu + 1, s);
                    enc = min(v + 1, 257);
                }
                g_start[s] = (lu << 9) | enc;
            }
            if (b == 16 && tid >= 512 && tid < 512 + (ILPAD - SLEN)) g_il[SLEN + (tid - 512)] = 0;
        }
    } else {
        // ============ density pipeline (blocks 0-15) ============
        // ---- rowprefix: rows r = b*16 + w (w<16), segment loads hoisted ----
        if (w < 16) {
            int r = b * 16 + w;
            int off = r * (r + 1) / 2;
            float v[8];
#pragma unroll
            for (int seg = 0; seg < 8; seg++) {
                int idx = seg * 32 + lane;
                v[seg] = (idx <= r) ? raw[off + idx] : 0.f;   // independent loads
            }
#pragma unroll
            for (int seg = 0; seg < 8; seg++) {
                int idx = seg * 32 + lane;
                v[seg] = (idx <= r) ? softplusf(v[seg]) : 0.f;
            }
            float carry = 0.f;
#pragma unroll
            for (int seg = 0; seg < 8; seg++) {
                if (seg * 32 <= r) {       // warp-uniform
                    float x = v[seg];
#pragma unroll
                    for (int o = 1; o < 32; o <<= 1) { float u = __shfl_up_sync(0xffffffffu, x, o); if (lane >= o) x += u; }
                    x += carry;
                    int idx = seg * 32 + lane;
                    if (idx <= r) g_P[off + idx] = x;
                    carry = __shfl_sync(0xffffffffu, x, 31);
                }
            }
            if (lane == 0) g_rowsum[r] = carry;
        }

        barrier_n(&g_sub_count, &g_sub_gen, 16);   // rowprefix -> colpre (blocks 0-15 only)

        if (b < 8) {
            // ---- colpreT, fully coalesced via smem transpose tile ----
            int J = b * 32;
            // load: warp w handles rows k = w, w+32, ... (coalesced 32-float rows)
#pragma unroll
            for (int seg = 0; seg < 8; seg++) {
                int k = seg * 32 + w;
                int j = J + lane;
                float val = (j <= k) ? g_P[k * (k + 1) / 2 + j] : 0.f;
                sm.cp.tile[k * 33 + lane] = val;
            }
            __syncthreads();
            // scan: warp w scans column j' = w over k (conflict-free via pad 33)
            {
                float v[8];
#pragma unroll
                for (int seg = 0; seg < 8; seg++) v[seg] = sm.cp.tile[(seg * 32 + lane) * 33 + w];
                float carry = 0.f;
#pragma unroll
                for (int seg = 0; seg < 8; seg++) {
                    float x = v[seg];
#pragma unroll
                    for (int o = 1; o < 32; o <<= 1) { float u = __shfl_up_sync(0xffffffffu, x, o); if (lane >= o) x += u; }
                    x += carry;
                    v[seg] = x;
                    carry = __shfl_sync(0xffffffffu, x, 31);
                }
#pragma unroll
                for (int seg = 0; seg < 8; seg++) sm.cp.tile[(seg * 32 + lane) * 33 + w] = v[seg];
            }
            __syncthreads();
            // store: warp w writes rows k = w, w+32, ... (coalesced)
#pragma unroll
            for (int seg = 0; seg < 8; seg++) {
                int k = seg * 32 + w;
                g_colpreT[k * NMESH + J + lane] = sm.cp.tile[k * 33 + lane];
            }
        } else if (b == 8 && w == 0) {
            // ---- A prefix of rowsums (one warp) ----
            float v[8];
#pragma unroll
            for (int seg = 0; seg < 8; seg++) v[seg] = g_rowsum[seg * 32 + lane];
            float carry = 0.f;
#pragma unroll
            for (int seg = 0; seg < 8; seg++) {
                float x = v[seg];
#pragma unroll
                for (int o = 1; o < 32; o <<= 1) { float u = __shfl_up_sync(0xffffffffu, x, o); if (lane >= o) x += u; }
                x += carry;
                g_A[seg * 32 + lane + 1] = x;
                carry = __shfl_sync(0xffffffffu, x, 31);
            }
            if (lane == 0) g_A[0] = 0.f;
        }
    }

    barrier_n(&g_bar_count, &g_bar_gen, NBLK);     // everything -> P3

    // ================= Phase 3: chain walk (all 32 blocks, 128 outputs each) ===========
    int t = b * 128 + tid;                 // 32*128 = 4096 outputs
    bool active = (tid < 128);
    int T = t + 1;
    int st = active ? g_start[T] : 0;      // issue early

    {
        const uint4* src = (const uint4*)g_il;
        uint4* dst = (uint4*)sm.walk.s_il;
        for (int i = tid; i < ILPAD / 4; i += TPB) dst[i] = src[i];
        for (int i = tid; i <= NMESH; i += TPB) sm.walk.s_A[i] = g_A[i];
    }
    __syncthreads();
    if (!active) return;

    int s = st >> 9;
    int Vmin = (st & 0x1FF) - 1;    // 256 acts as +inf
    int lo = 0;
    float acc = 0.f;
    bool finished = false;

    while (!finished) {
        // ---- Phase A: LDS-only chase; record (lo, hi, V) per level ----
        int hiA[CHUNK], VA[CHUNK], loA[CHUNK];
        bool act[CHUNK];
        bool done = false;
#pragma unroll
        for (int c = 0; c < CHUNK; c++) {
            act[c] = !done;
            if (!done) {
                int il = sm.walk.s_il[s];
                int hi = (unsigned)il >> 22;
                hiA[c] = hi; VA[c] = Vmin; loA[c] = lo;
                if (hi >= NMESH - 1) done = true;
                else {
                    Vmin = min(Vmin, (il & 0x1FF) - 1);
                    s = ((il >> 9) & 0x1FFF) - 1;
                    lo = hi;
                }
            } else { hiA[c] = 0; VA[c] = -1; loA[c] = 0; }
        }

        // ---- Phase B: batched independent colpre/A accumulation ----
        float a0 = 0.f, a1 = 0.f, a2 = 0.f, a3 = 0.f;
#pragma unroll
        for (int c = 0; c < CHUNK; c++) {
            float contrib = 0.f;
            if (act[c]) {
                int hi = hiA[c], V = VA[c], lol = loA[c];
                if (V >= hi - 1) {
                    contrib = sm.walk.s_A[hi] - sm.walk.s_A[lol];
                } else if (V >= 0) {
                    int m = max(lol, V + 1);
                    contrib = sm.walk.s_A[m] - sm.walk.s_A[lol]
                            + g_colpreT[(hi - 1) * NMESH + V]
                            - g_colpreT[(m - 1) * NMESH + V];
                }
            }
            if ((c & 3) == 0) a0 += contrib;
            else if ((c & 3) == 1) a1 += contrib;
            else if ((c & 3) == 2) a2 += contrib;
            else a3 += contrib;
        }
        acc += (a0 + a1) + (a2 + a3);
        finished = done;
    }

    float S = sm.walk.s_A[NMESH];
    out[t] = (2.f * acc - S) / S;
}

// ---------------- launch: single fused kernel ----------------
extern "C" void kernel_launch(void* const* d_in, const int* in_sizes, int n_in,
                              void* d_out, int out_size) {
    const float* h   = nullptr;
    const float* raw = nullptr;
    const float* m2  = nullptr;
    const float* m3  = nullptr;
    for (int i = 0; i < n_in; i++) {
        if (in_sizes[i] == MSTEPS && !h)            h   = (const float*)d_in[i];
        else if (in_sizes[i] == TRI && !raw)        raw = (const float*)d_in[i];
        else if (in_sizes[i] == NMESH * NMESH) {
            if (!m2) m2 = (const float*)d_in[i];
            else     m3 = (const float*)d_in[i];
        }
    }
    if (!m3) m3 = m2;

    k_fused<<<NBLK, TPB>>>(h, raw, m2, m3, (float*)d_out);
}

// round 14
// speedup vs baseline: 4.8596x; 1.0019x over previous
#include <cuda_runtime.h>
#include <math.h>
#include <limits.h>

#define NMESH  256
#define MSTEPS 4096
#define SLEN   (MSTEPS + 1)     // scan steps 0..M (step 0 = pseudo init sweep-up at hc=1.0)
#define SLENP  4128             // padded to multiple of 32 (129 chunks)
#define NCH    (SLENP / 32)     // 129
#define NCHP   136
#define TRI    (NMESH * (NMESH + 1) / 2)
#define SENTD  32767
#define CHUNK  8
#define ILPAD  4112             // SLEN padded to multiple of 4 for uint4 copy
#define NWORK  32               // working blocks
#define NGRID  148              // launch grid (defeats low-grid issue throttle)
#define NSUB   9                // density sub-barrier participants (blocks 0-8)
#define TPB    1024

// ---------------- device scratch ----------------
__device__ float  g_P[TRI];                   // per-row inclusive prefix of softplus density
__device__ float  g_rowsum[NMESH];
__device__ int    g_il[ILPAD];                // packed: (iu:9)<<22 | (link+1:13)<<9 | (segMin+1:9)
__device__ int    g_start[SLEN];              // packed: lastup<<9 | (dminLast+1)
__device__ float  g_A[NMESH + 1];             // prefix of rowsums; g_A[NMESH] = S
__device__ float  g_colpreT[NMESH * NMESH];   // colpreT[k*N+j] = sum_{r=j..k} P_r(j)

// barriers (generation-based; persist across graph replays)
__device__ volatile int g_bar_count = 0, g_bar_gen = 0;   // full (NWORK blocks)
__device__ volatile int g_sub_count = 0, g_sub_gen = 0;   // density group (NSUB blocks)

__device__ __forceinline__ void barrier_n(volatile int* cnt, volatile int* gen, int target) {
    __syncthreads();
    if (threadIdx.x == 0) {
        int g = *gen;
        __threadfence();
        if (atomicAdd((int*)cnt, 1) == target - 1) {
            *cnt = 0;
            __threadfence();
            *gen = g + 1;
        } else {
            while (*gen == g) { }   // pure spin: fastest wake
        }
        __threadfence();
    }
    __syncthreads();
}

__device__ __forceinline__ float softplusf(float x) {
    return fmaxf(x, 0.f) + log1pf(expf(-fabsf(x)));
}

// shared-memory overlay
union SMem {
    struct {   // meta pipeline, blocks 16-31 (redundant metaA + local partB)
        float lin[NMESH];
        short s_iu[SLENP];
        short s_d[SLENP];
        short s_lu[SLENP];
        short pmind[SLENP];
        short smind[SLENP];
        short cmind[NCHP];
        short cmaxu[NCHP];
        int   sc[32];
    } meta;
    struct {   // colpre tile, blocks 0-7
        float tile[NMESH * 33];   // padded stride 33 -> conflict-free column access
    } cp;
    struct {   // phase 3, all working blocks
        int   s_il[ILPAD];
        float s_A[NMESH + 1];
    } walk;
};

// range-min of d over [l, r] using chunk tables (all smem, unrolled in-chunk)
__device__ __forceinline__ int rmin_d(const short* s_d, const short* pmind,
                                      const short* smind, const short* cmind,
                                      int l, int r) {
    int cl = l >> 5, cr = r >> 5;
    if (cl == cr) {
        int v = SENTD;
        int base = cl << 5;
#pragma unroll
        for (int ii = 0; ii < 32; ii++) {
            int idx = base + ii;
            int dv = s_d[idx];                    // independent LDS
            if (idx >= l && idx <= r) v = min(v, dv);
        }
        return v;
    }
    int v = min((int)smind[l], (int)pmind[r]);
    for (int cc = cl + 1; cc < cr; cc++) v = min(v, (int)cmind[cc]);
    return v;
}

__global__ void __launch_bounds__(TPB, 1) k_fused(const float* __restrict__ h,
                                                  const float* __restrict__ raw,
                                                  const float* __restrict__ m2,
                                                  const float* __restrict__ m3,
                                                  float* __restrict__ out) {
    int b = blockIdx.x;
    if (b >= NWORK) return;     // padding blocks (grid=148 defeats low-grid throttle)

    __shared__ SMem sm;
    int tid = threadIdx.x;
    int lane = tid & 31, w = tid >> 5;

    if (b >= 16) {
        // ============ meta pipeline (blocks 16-31, fully local) ============
        if (tid < NMESH) {
            const float* xx = (m2[1] != m2[0]) ? m2 : m3;
            sm.meta.lin[tid] = xx[tid];
        }
        __syncthreads();

        // ---- classification: arithmetic candidate + exact fixup on mesh floats ----
        for (int s = tid; s < SLENP; s += TPB) {
            short iu = 0, dd = (short)SENTD;
            if (s < SLEN) {
                float hc, hp;
                if (s == 0) { hc = 1.0f; hp = h[MSTEPS - 1]; }
                else { hc = h[s - 1]; hp = (s == 1) ? 1.0f : h[s - 2]; }
                if (hc > hp) {
                    int m = (int)((hc + 1.0f) * 127.5f);
                    m = min(max(m, 0), 255);
                    while (m > 0 && sm.meta.lin[m - 1] >= hc) m--;
                    while (m < 256 && sm.meta.lin[m] < hc) m++;
                    iu = (short)m;
                } else if (hc < hp) {
                    int m = (int)((hc + 1.0f) * 127.5f);
                    m = min(max(m, 0), 255);
                    while (m > 0 && sm.meta.lin[m - 1] > hc) m--;
                    while (m < 256 && sm.meta.lin[m] <= hc) m++;
                    dd = (short)(m - 1);
                }
            }
            sm.meta.s_iu[s] = iu; sm.meta.s_d[s] = dd;
        }
        __syncthreads();

        // ---- lastup local + chunk mins fused (one barrier serves both) ----
        int v_lu;
        int l0, l1, l2, l3;
        {
            int base = tid * 4;
            int w0 = (sm.meta.s_iu[base]     > 0) ? base     : -1;
            int w1 = (sm.meta.s_iu[base + 1] > 0) ? base + 1 : -1;
            int w2 = (sm.meta.s_iu[base + 2] > 0) ? base + 2 : -1;
            int w3 = (sm.meta.s_iu[base + 3] > 0) ? base + 3 : -1;
            l0 = w0; l1 = max(l0, w1); l2 = max(l1, w2); l3 = max(l2, w3);
            v_lu = l3;
#pragma unroll
            for (int o = 1; o < 32; o <<= 1) { int u = __shfl_up_sync(0xffffffffu, v_lu, o); if (lane >= o) v_lu = max(v_lu, u); }
            if (lane == 31) sm.meta.sc[w] = v_lu;
        }
        // chunk mins (independent of lastup scan; reads s_iu/s_d only)
        for (int c = w; c < NCH; c += 32) {
            int e = c * 32 + lane;
            int dv = sm.meta.s_d[e];
            int uv = sm.meta.s_iu[e];
            int p = dv;
#pragma unroll
            for (int o = 1; o < 32; o <<= 1) { int u = __shfl_up_sync(0xffffffffu, p, o); if (lane >= o) p = min(p, u); }
            sm.meta.pmind[e] = (short)p;
            int q = dv;
#pragma unroll
            for (int o = 1; o < 32; o <<= 1) { int u = __shfl_down_sync(0xffffffffu, q, o); if (lane + o < 32) q = min(q, u); }
            sm.meta.smind[e] = (short)q;
            if (lane == 31) sm.meta.cmind[c] = (short)p;
            int m = uv;
#pragma unroll
            for (int o = 16; o >= 1; o >>= 1) m = max(m, __shfl_xor_sync(0xffffffffu, m, o));
            if (lane == 0) sm.meta.cmaxu[c] = (short)m;
        }
        __syncthreads();
        if (w == 0) {
            int x = sm.meta.sc[lane];
#pragma unroll
            for (int o = 1; o < 32; o <<= 1) { int u = __shfl_up_sync(0xffffffffu, x, o); if (lane >= o) x = max(x, u); }
            sm.meta.sc[lane] = x;
        }
        __syncthreads();
        {
            int base = tid * 4;
            int warppre = (w > 0) ? sm.meta.sc[w - 1] : INT_MIN;
            int lanepre = __shfl_up_sync(0xffffffffu, v_lu, 1);
            int pre = (lane == 0) ? warppre : max(warppre, lanepre);
            sm.meta.s_lu[base]     = (short)max(pre, l0);
            sm.meta.s_lu[base + 1] = (short)max(pre, l1);
            sm.meta.s_lu[base + 2] = (short)max(pre, l2);
            sm.meta.s_lu[base + 3] = (short)max(pre, l3);
            if (tid == TPB - 1) {
                int w4 = (sm.meta.s_iu[4096] > 0) ? 4096 : -1;
                sm.meta.s_lu[4096] = (short)max(max(pre, l3), w4);
            }
        }
        __syncthreads();

        // ---- partB: each block handles 257 s-values from its local tables ----
        {
            int s = (b - 16) * 257 + tid;
            if (tid < 257 && s < SLEN) {
                int iu = sm.meta.s_iu[s];
                int lnk = -1;
                int e = 257;                              // segMin+1 encoding; 257 = +inf
                if (iu > 0 && iu < NMESH - 1) {
                    // PGE: rightmost s' < s with iu[s'] > iu (unrolled independent LDS)
                    int ci = (s - 1) >> 5;
                    int base = ci << 5;
                    int found = -1;
#pragma unroll
                    for (int ii = 0; ii < 32; ii++) {
                        int idx = base + ii;
                        int val = sm.meta.s_iu[idx];
                        if (idx < s && val > iu) found = idx;
                    }
                    if (found < 0) {
                        int c = ci - 1;
                        while ((int)sm.meta.cmaxu[c] <= iu) c--;
                        base = c << 5;
#pragma unroll
                        for (int ii = 0; ii < 32; ii++) {
                            int idx = base + ii;
                            int val = sm.meta.s_iu[idx];
                            if (val > iu) found = idx;
                        }
                    }
                    lnk = found;
                    int v = rmin_d(sm.meta.s_d, sm.meta.pmind, sm.meta.smind, sm.meta.cmind, lnk + 1, s);
                    e = min(v + 1, 257);
                }
                g_il[s] = (iu << 22) | ((lnk + 1) << 9) | e;

                // g_start: lastup + min d over (lastup, s]
                int lu = sm.meta.s_lu[s];
                int enc = 257;
                if (lu < s) {
                    int v = rmin_d(sm.meta.s_d, sm.meta.pmind, sm.meta.smind, sm.meta.cmind, lu + 1, s);
                    enc = min(v + 1, 257);
                }
                g_start[s] = (lu << 9) | enc;
            }
            if (b == 16 && tid >= 512 && tid < 512 + (ILPAD - SLEN)) g_il[SLEN + (tid - 512)] = 0;
        }
    } else if (b < NSUB) {
        // ============ density pipeline (blocks 0-8) ============
        // ---- rowprefix: blocks 0-7, all 32 warps, one row each ----
        if (b < 8) {
            int r = b * 32 + w;
            int off = r * (r + 1) / 2;
            float v[8];
#pragma unroll
            for (int seg = 0; seg < 8; seg++) {
                int idx = seg * 32 + lane;
                v[seg] = (idx <= r) ? raw[off + idx] : 0.f;   // independent loads
            }
#pragma unroll
            for (int seg = 0; seg < 8; seg++) {
                int idx = seg * 32 + lane;
                v[seg] = (idx <= r) ? softplusf(v[seg]) : 0.f;
            }
            float carry = 0.f;
#pragma unroll
            for (int seg = 0; seg < 8; seg++) {
                if (seg * 32 <= r) {       // warp-uniform
                    float x = v[seg];
#pragma unroll
                    for (int o = 1; o < 32; o <<= 1) { float u = __shfl_up_sync(0xffffffffu, x, o); if (lane >= o) x += u; }
                    x += carry;
                    int idx = seg * 32 + lane;
                    if (idx <= r) g_P[off + idx] = x;
                    carry = __shfl_sync(0xffffffffu, x, 31);
                }
            }
            if (lane == 0) g_rowsum[r] = carry;
        }

        barrier_n(&g_sub_count, &g_sub_gen, NSUB);   // rowprefix -> colpre (blocks 0-8)

        if (b < 8) {
            // ---- colpreT, fully coalesced via smem transpose tile ----
            int J = b * 32;
#pragma unroll
            for (int seg = 0; seg < 8; seg++) {
                int k = seg * 32 + w;
                int j = J + lane;
                float val = (j <= k) ? g_P[k * (k + 1) / 2 + j] : 0.f;
                sm.cp.tile[k * 33 + lane] = val;
            }
            __syncthreads();
            {
                float v[8];
#pragma unroll
                for (int seg = 0; seg < 8; seg++) v[seg] = sm.cp.tile[(seg * 32 + lane) * 33 + w];
                float carry = 0.f;
#pragma unroll
                for (int seg = 0; seg < 8; seg++) {
                    float x = v[seg];
#pragma unroll
                    for (int o = 1; o < 32; o <<= 1) { float u = __shfl_up_sync(0xffffffffu, x, o); if (lane >= o) x += u; }
                    x += carry;
                    v[seg] = x;
                    carry = __shfl_sync(0xffffffffu, x, 31);
                }
#pragma unroll
                for (int seg = 0; seg < 8; seg++) sm.cp.tile[(seg * 32 + lane) * 33 + w] = v[seg];
            }
            __syncthreads();
#pragma unroll
            for (int seg = 0; seg < 8; seg++) {
                int k = seg * 32 + w;
                g_colpreT[k * NMESH + J + lane] = sm.cp.tile[k * 33 + lane];
            }
        } else if (w == 0) {
            // ---- block 8: A prefix of rowsums (one warp) ----
            float v[8];
#pragma unroll
            for (int seg = 0; seg < 8; seg++) v[seg] = g_rowsum[seg * 32 + lane];
            float carry = 0.f;
#pragma unroll
            for (int seg = 0; seg < 8; seg++) {
                float x = v[seg];
#pragma unroll
                for (int o = 1; o < 32; o <<= 1) { float u = __shfl_up_sync(0xffffffffu, x, o); if (lane >= o) x += u; }
                x += carry;
                g_A[seg * 32 + lane + 1] = x;
                carry = __shfl_sync(0xffffffffu, x, 31);
            }
            if (lane == 0) g_A[0] = 0.f;
        }
    }
    // blocks 9-15: no phase-1/2 work, fall straight to the full barrier

    barrier_n(&g_bar_count, &g_bar_gen, NWORK);     // everything -> P3

    // ================= Phase 3: chain walk (32 blocks, 128 outputs each) ===========
    int t = b * 128 + tid;                 // 32*128 = 4096 outputs
    bool active = (tid < 128);
    int T = t + 1;
    int st = active ? g_start[T] : 0;      // issue early

    {
        const uint4* src = (const uint4*)g_il;
        uint4* dst = (uint4*)sm.walk.s_il;
        for (int i = tid; i < ILPAD / 4; i += TPB) dst[i] = src[i];
        for (int i = tid; i <= NMESH; i += TPB) sm.walk.s_A[i] = g_A[i];
    }
    __syncthreads();
    if (!active) return;

    int s = st >> 9;
    int Vmin = (st & 0x1FF) - 1;    // 256 acts as +inf
    int lo = 0;
    float acc = 0.f;
    bool finished = false;

    while (!finished) {
        // ---- Phase A: LDS-only chase; record (lo, hi, V) per level ----
        int hiA[CHUNK], VA[CHUNK], loA[CHUNK];
        bool act[CHUNK];
        bool done = false;
#pragma unroll
        for (int c = 0; c < CHUNK; c++) {
            act[c] = !done;
            if (!done) {
                int il = sm.walk.s_il[s];
                int hi = (unsigned)il >> 22;
                hiA[c] = hi; VA[c] = Vmin; loA[c] = lo;
                if (hi >= NMESH - 1) done = true;
                else {
                    Vmin = min(Vmin, (il & 0x1FF) - 1);
                    s = ((il >> 9) & 0x1FFF) - 1;
                    lo = hi;
                }
            } else { hiA[c] = 0; VA[c] = -1; loA[c] = 0; }
        }

        // ---- Phase B: batched independent colpre/A accumulation ----
        float a0 = 0.f, a1 = 0.f, a2 = 0.f, a3 = 0.f;
#pragma unroll
        for (int c = 0; c < CHUNK; c++) {
            float contrib = 0.f;
            if (act[c]) {
                int hi = hiA[c], V = VA[c], lol = loA[c];
                if (V >= hi - 1) {
                    contrib = sm.walk.s_A[hi] - sm.walk.s_A[lol];
                } else if (V >= 0) {
                    int m = max(lol, V + 1);
                    contrib = sm.walk.s_A[m] - sm.walk.s_A[lol]
                            + g_colpreT[(hi - 1) * NMESH + V]
                            - g_colpreT[(m - 1) * NMESH + V];
                }
            }
            if ((c & 3) == 0) a0 += contrib;
            else if ((c & 3) == 1) a1 += contrib;
            else if ((c & 3) == 2) a2 += contrib;
            else a3 += contrib;
        }
        acc += (a0 + a1) + (a2 + a3);
        finished = done;
    }

    float S = sm.walk.s_A[NMESH];
    out[t] = (2.f * acc - S) / S;
}

// ---------------- launch: single fused kernel, padded grid ----------------
extern "C" void kernel_launch(void* const* d_in, const int* in_sizes, int n_in,
                              void* d_out, int out_size) {
    const float* h   = nullptr;
    const float* raw = nullptr;
    const float* m2  = nullptr;
    const float* m3  = nullptr;
    for (int i = 0; i < n_in; i++) {
        if (in_sizes[i] == MSTEPS && !h)            h   = (const float*)d_in[i];
        else if (in_sizes[i] == TRI && !raw)        raw = (const float*)d_in[i];
        else if (in_sizes[i] == NMESH * NMESH) {
            if (!m2) m2 = (const float*)d_in[i];
            else     m3 = (const float*)d_in[i];
        }
    }
    if (!m3) m3 = m2;

    k_fused<<<NGRID, TPB>>>(h, raw, m2, m3, (float*)d_out);
}